// round 4
// baseline (speedup 1.0000x reference)
#include <cuda_runtime.h>
#include <cuda_bf16.h>
#include <stdint.h>
#include <math.h>

#define BATCH 8
#define SEQ   2048
#define DIM   1024
#define MTOT  (BATCH * SEQ)

// ---------------------------------------------------------------------------
// Static device scratch (allocation-free contract).
// ---------------------------------------------------------------------------
__device__ __align__(256) __nv_bfloat16 g_xh[(size_t)MTOT * DIM];
__device__ __align__(256) __nv_bfloat16 g_xl[(size_t)MTOT * DIM];
__device__ __align__(256) __nv_bfloat16 g_Wth[4][(size_t)DIM * DIM];
__device__ __align__(256) __nv_bfloat16 g_Wtl[4][(size_t)DIM * DIM];
__device__ __align__(256) __nv_bfloat16 g_Qh[(size_t)MTOT * DIM];
__device__ __align__(256) __nv_bfloat16 g_Ql[(size_t)MTOT * DIM];
__device__ __align__(256) __nv_bfloat16 g_Kh[(size_t)MTOT * DIM];
__device__ __align__(256) __nv_bfloat16 g_Kl[(size_t)MTOT * DIM];
__device__ __align__(256) __nv_bfloat16 g_Vh[(size_t)MTOT * DIM];
__device__ __align__(256) __nv_bfloat16 g_Vl[(size_t)MTOT * DIM];
__device__ __align__(256) __nv_bfloat16 g_Vth[(size_t)MTOT * DIM];
__device__ __align__(256) __nv_bfloat16 g_Vtl[(size_t)MTOT * DIM];
__device__ __align__(256) __nv_bfloat16 g_Oh[(size_t)MTOT * DIM];
__device__ __align__(256) __nv_bfloat16 g_Ol[(size_t)MTOT * DIM];
__device__ __align__(256) float          g_S [(size_t)BATCH * SEQ * SEQ];
__device__ __align__(256) __nv_bfloat16 g_Ph[(size_t)BATCH * SEQ * SEQ];
__device__ __align__(256) __nv_bfloat16 g_Pl[(size_t)BATCH * SEQ * SEQ];

// ---------------------------------------------------------------------------
// Helpers (arch-agnostic PTX only: cp.async / ldmatrix / mma.sync)
// ---------------------------------------------------------------------------
__device__ __forceinline__ uint32_t smem_to_u32(const void* smem_ptr) {
    uint32_t addr;
    asm("{ .reg .u64 tmp; cvta.to.shared.u64 tmp, %1; cvt.u32.u64 %0, tmp; }"
        : "=r"(addr) : "l"(smem_ptr));
    return addr;
}
#define SMEM_SWIZZLE_128B(byte_offset) \
    ((byte_offset) ^ (((byte_offset) >> 3) & 0x70))
#define CP_ASYNC_16(dst_u32, src_ptr) \
    asm volatile("cp.async.cg.shared.global [%0], [%1], 16;" \
                 :: "r"(dst_u32), "l"(src_ptr) : "memory")
#define CP_COMMIT() asm volatile("cp.async.commit_group;" ::: "memory")
#define CP_WAIT(n)  asm volatile("cp.async.wait_group %0;" :: "n"(n) : "memory")

#define LDMATRIX_X4(r0, r1, r2, r3, addr) \
    asm volatile("ldmatrix.sync.aligned.m8n8.x4.shared.b16 {%0,%1,%2,%3}, [%4];" \
                 : "=r"(r0), "=r"(r1), "=r"(r2), "=r"(r3) : "r"(addr))

#define MMA_BF16(c, a, b0, b1) \
    asm volatile("mma.sync.aligned.m16n8k16.row.col.f32.bf16.bf16.f32 " \
                 "{%0,%1,%2,%3}, {%4,%5,%6,%7}, {%8,%9}, {%0,%1,%2,%3};" \
                 : "+f"((c)[0]), "+f"((c)[1]), "+f"((c)[2]), "+f"((c)[3]) \
                 : "r"((a)[0]), "r"((a)[1]), "r"((a)[2]), "r"((a)[3]), \
                   "r"(b0), "r"(b1))

// ---------------------------------------------------------------------------
// GEMM: D[M,N] = A@B^T with 3-term bf16 split folded into K_eff = 3K.
//   A_hi/A_lo: [M,K] K-major bf16 ; B_hi/B_lo: [N,K] K-major bf16
// Tile 128x128, BK=64 bf16 (128B rows, SW128), 3-stage cp.async pipeline,
// 8 warps (4 m x 2 n), warp tile 32x64 via m16n8k16 HMMA. 2 CTAs/SM.
// EPI: 0 = fp32 out, 1 = fp32 + bias, 2 = split bf16 hi/lo out.
// ---------------------------------------------------------------------------
#define TILE_BYTES 16384            // 128 rows x 128B
#define STAGE_BYTES (2 * TILE_BYTES)
#define STAGES 3
#define SM_TOTAL (STAGES * STAGE_BYTES)   // 98304

template <int EPI>
__global__ void __launch_bounds__(256, 2)
gemm3_kernel(const __nv_bfloat16* __restrict__ Ah, const __nv_bfloat16* __restrict__ Al,
             const __nv_bfloat16* __restrict__ Bh, const __nv_bfloat16* __restrict__ Bl,
             float* __restrict__ Cf,
             __nv_bfloat16* __restrict__ Ch, __nv_bfloat16* __restrict__ Cl,
             const float* __restrict__ bias,
             int K, int ldC, size_t sA, size_t sB, size_t sC)
{
    extern __shared__ char smem[];
    const uint32_t smem_u = smem_to_u32(smem);
    const int tid = threadIdx.x;
    const int lane = tid & 31;
    const int wid = tid >> 5;
    const int warp_m = wid & 3;          // 4 warps down M (32 rows each)
    const int warp_n = wid >> 2;         // 2 warps across N (64 cols each)
    const int rowBase = blockIdx.y * 128;
    const int colBase = blockIdx.x * 128;
    const size_t zA = (size_t)blockIdx.z * sA;
    const size_t zB = (size_t)blockIdx.z * sB;
    const size_t zC = (size_t)blockIdx.z * sC;

    const int ldr_row0 = tid >> 3;       // rows tid/8, +32, +64, +96
    const int ldr_ch   = tid & 7;

    float acc[2][8][4];
#pragma unroll
    for (int i = 0; i < 2; i++)
#pragma unroll
        for (int j = 0; j < 8; j++)
#pragma unroll
            for (int e = 0; e < 4; e++) acc[i][j][e] = 0.0f;

    const int nk = K >> 6;
    const int nIter = 3 * nk;

    auto issue_load = [&](int i) {
        const int stage = i % STAGES;
        const int seg = i / nk;
        const int kk = (i - seg * nk) << 6;
        const __nv_bfloat16* As = ((seg == 1) ? Al : Ah) + zA;
        const __nv_bfloat16* Bs = ((seg == 2) ? Bl : Bh) + zB;
        const uint32_t aBase = smem_u + stage * STAGE_BYTES;
        const uint32_t bBase = aBase + TILE_BYTES;
#pragma unroll
        for (int p = 0; p < 4; p++) {
            const int row = ldr_row0 + p * 32;
            const uint32_t soff = SMEM_SWIZZLE_128B((uint32_t)row * 128 + ldr_ch * 16);
            CP_ASYNC_16(aBase + soff,
                        As + (size_t)(rowBase + row) * K + kk + ldr_ch * 8);
            CP_ASYNC_16(bBase + soff,
                        Bs + (size_t)(colBase + row) * K + kk + ldr_ch * 8);
        }
    };

    // Prologue: stages 0 and 1 in flight
    issue_load(0); CP_COMMIT();
    issue_load(1); CP_COMMIT();

    for (int i = 0; i < nIter; i++) {
        CP_WAIT(1);                 // groups 0..i complete -> stage i ready
        __syncthreads();            // all warps done with stage (i-1)%3 compute
        if (i + 2 < nIter) issue_load(i + 2);
        CP_COMMIT();                // unconditional: keeps group numbering exact

        const uint32_t aBase = smem_u + (i % STAGES) * STAGE_BYTES;
        const uint32_t bBase = aBase + TILE_BYTES;
#pragma unroll
        for (int ks = 0; ks < 4; ks++) {
            const uint32_t k2 = ks * 32;           // byte offset within 128B row
            uint32_t a[2][4];
#pragma unroll
            for (int fm = 0; fm < 2; fm++) {
                const uint32_t row = warp_m * 32 + fm * 16 + (lane & 15);
                const uint32_t addr = aBase +
                    SMEM_SWIZZLE_128B(row * 128 + k2 + ((lane >> 4) << 4));
                LDMATRIX_X4(a[fm][0], a[fm][1], a[fm][2], a[fm][3], addr);
            }
#pragma unroll
            for (int fn2 = 0; fn2 < 4; fn2++) {
                const uint32_t n = warp_n * 64 + fn2 * 16 + (lane & 7) + ((lane >> 4) << 3);
                const uint32_t addr = bBase +
                    SMEM_SWIZZLE_128B(n * 128 + k2 + (((lane >> 3) & 1) << 4));
                uint32_t b0, b1, b2, b3;
                LDMATRIX_X4(b0, b1, b2, b3, addr);
                MMA_BF16(acc[0][fn2 * 2 + 0], a[0], b0, b1);
                MMA_BF16(acc[0][fn2 * 2 + 1], a[0], b2, b3);
                MMA_BF16(acc[1][fn2 * 2 + 0], a[1], b0, b1);
                MMA_BF16(acc[1][fn2 * 2 + 1], a[1], b2, b3);
            }
        }
    }

    // Epilogue
    const int gid = lane >> 2;
    const int tig = lane & 3;
#pragma unroll
    for (int fm = 0; fm < 2; fm++) {
#pragma unroll
        for (int fn = 0; fn < 8; fn++) {
            const int r0 = rowBase + warp_m * 32 + fm * 16 + gid;
            const int c  = colBase + warp_n * 64 + fn * 8 + tig * 2;
            const float* ac = acc[fm][fn];
            if (EPI == 2) {
                __nv_bfloat162 h0 = __floats2bfloat162_rn(ac[0], ac[1]);
                float2 hf0 = __bfloat1622float2(h0);
                __nv_bfloat162 l0 = __floats2bfloat162_rn(ac[0] - hf0.x, ac[1] - hf0.y);
                __nv_bfloat162 h1 = __floats2bfloat162_rn(ac[2], ac[3]);
                float2 hf1 = __bfloat1622float2(h1);
                __nv_bfloat162 l1 = __floats2bfloat162_rn(ac[2] - hf1.x, ac[3] - hf1.y);
                *(uint32_t*)(Ch + zC + (size_t)r0 * ldC + c)       = *(uint32_t*)&h0;
                *(uint32_t*)(Cl + zC + (size_t)r0 * ldC + c)       = *(uint32_t*)&l0;
                *(uint32_t*)(Ch + zC + (size_t)(r0 + 8) * ldC + c) = *(uint32_t*)&h1;
                *(uint32_t*)(Cl + zC + (size_t)(r0 + 8) * ldC + c) = *(uint32_t*)&l1;
            } else {
                float2 v0 = make_float2(ac[0], ac[1]);
                float2 v1 = make_float2(ac[2], ac[3]);
                if (EPI == 1) {
                    const float b0 = bias[c], b1 = bias[c + 1];
                    v0.x += b0; v0.y += b1;
                    v1.x += b0; v1.y += b1;
                }
                *(float2*)(Cf + zC + (size_t)r0 * ldC + c)       = v0;
                *(float2*)(Cf + zC + (size_t)(r0 + 8) * ldC + c) = v1;
            }
        }
    }
}

// ---------------------------------------------------------------------------
// fp32 -> bf16 hi/lo split (elementwise)
// ---------------------------------------------------------------------------
__global__ void __launch_bounds__(256)
split_fp32_kernel(const float* __restrict__ x,
                  __nv_bfloat16* __restrict__ h, __nv_bfloat16* __restrict__ l)
{
    size_t i = ((size_t)blockIdx.x * 256 + threadIdx.x) * 4;
    float4 v = *(const float4*)(x + i);
    float vv[4] = {v.x, v.y, v.z, v.w};
    __nv_bfloat16 hh[4], ll[4];
#pragma unroll
    for (int j = 0; j < 4; j++) {
        hh[j] = __float2bfloat16(vv[j]);
        ll[j] = __float2bfloat16(vv[j] - __bfloat162float(hh[j]));
    }
    *(uint2*)(h + i) = *(uint2*)hh;
    *(uint2*)(l + i) = *(uint2*)ll;
}

// ---------------------------------------------------------------------------
// Transpose fp32 W [DIM,DIM] -> split bf16 Wt hi/lo (Wt[e,d] = W[d,e])
// ---------------------------------------------------------------------------
__global__ void __launch_bounds__(256)
transW_kernel(const float* __restrict__ W,
              __nv_bfloat16* __restrict__ th, __nv_bfloat16* __restrict__ tl)
{
    __shared__ float t[32][33];
    const int tx = threadIdx.x, ty = threadIdx.y;
    const int x = blockIdx.x * 32 + tx;
    const int y0 = blockIdx.y * 32;
#pragma unroll
    for (int p = 0; p < 4; p++)
        t[ty + 8 * p][tx] = W[(size_t)(y0 + ty + 8 * p) * DIM + x];
    __syncthreads();
    const int ox = blockIdx.y * 32 + tx;
    const int oy0 = blockIdx.x * 32;
#pragma unroll
    for (int p = 0; p < 4; p++) {
        float v = t[tx][ty + 8 * p];
        __nv_bfloat16 h = __float2bfloat16(v);
        __nv_bfloat16 l = __float2bfloat16(v - __bfloat162float(h));
        th[(size_t)(oy0 + ty + 8 * p) * DIM + ox] = h;
        tl[(size_t)(oy0 + ty + 8 * p) * DIM + ox] = l;
    }
}

// ---------------------------------------------------------------------------
// Transpose bf16 pair per batch: V [SEQ,DIM] -> Vt [DIM,SEQ]
// ---------------------------------------------------------------------------
__global__ void __launch_bounds__(256)
transV_kernel(const __nv_bfloat16* __restrict__ ih, const __nv_bfloat16* __restrict__ il,
              __nv_bfloat16* __restrict__ oh, __nv_bfloat16* __restrict__ ol)
{
    __shared__ __nv_bfloat16 t0[32][33];
    __shared__ __nv_bfloat16 t1[32][33];
    const size_t zin = (size_t)blockIdx.z * SEQ * DIM;
    const int tx = threadIdx.x, ty = threadIdx.y;
    const int x = blockIdx.x * 32 + tx;
    const int y0 = blockIdx.y * 32;
#pragma unroll
    for (int p = 0; p < 4; p++) {
        t0[ty + 8 * p][tx] = ih[zin + (size_t)(y0 + ty + 8 * p) * DIM + x];
        t1[ty + 8 * p][tx] = il[zin + (size_t)(y0 + ty + 8 * p) * DIM + x];
    }
    __syncthreads();
    const int ox = blockIdx.y * 32 + tx;
    const int oy0 = blockIdx.x * 32;
#pragma unroll
    for (int p = 0; p < 4; p++) {
        oh[zin + (size_t)(oy0 + ty + 8 * p) * SEQ + ox] = t0[tx][ty + 8 * p];
        ol[zin + (size_t)(oy0 + ty + 8 * p) * SEQ + ox] = t1[tx][ty + 8 * p];
    }
}

// ---------------------------------------------------------------------------
// Row softmax (SEQ=2048 cols) with scale; emits split-bf16 P
// ---------------------------------------------------------------------------
__global__ void __launch_bounds__(256)
softmax_split_kernel(const float* __restrict__ S,
                     __nv_bfloat16* __restrict__ Ph, __nv_bfloat16* __restrict__ Pl,
                     float scale_log2e)
{
    const size_t row = blockIdx.x;
    const float* p = S + row * SEQ;
    const int tid = threadIdx.x;

    float vals[8];
    float lmax = -INFINITY;
#pragma unroll
    for (int i = 0; i < 8; i++) {
        float v = p[tid + i * 256] * scale_log2e;   // log2-domain logits
        vals[i] = v;
        lmax = fmaxf(lmax, v);
    }
    __shared__ float red[8];
#pragma unroll
    for (int o = 16; o > 0; o >>= 1)
        lmax = fmaxf(lmax, __shfl_xor_sync(0xffffffffu, lmax, o));
    if ((tid & 31) == 0) red[tid >> 5] = lmax;
    __syncthreads();
    float m = red[0];
#pragma unroll
    for (int w = 1; w < 8; w++) m = fmaxf(m, red[w]);
    __syncthreads();

    float lsum = 0.0f;
#pragma unroll
    for (int i = 0; i < 8; i++) {
        vals[i] = exp2f(vals[i] - m);
        lsum += vals[i];
    }
#pragma unroll
    for (int o = 16; o > 0; o >>= 1)
        lsum += __shfl_xor_sync(0xffffffffu, lsum, o);
    if ((tid & 31) == 0) red[tid >> 5] = lsum;
    __syncthreads();
    float tot = 0.0f;
#pragma unroll
    for (int w = 0; w < 8; w++) tot += red[w];
    const float rinv = 1.0f / tot;

#pragma unroll
    for (int i = 0; i < 8; i++) {
        float v = vals[i] * rinv;
        __nv_bfloat16 h = __float2bfloat16(v);
        __nv_bfloat16 l = __float2bfloat16(v - __bfloat162float(h));
        Ph[row * SEQ + tid + i * 256] = h;
        Pl[row * SEQ + tid + i * 256] = l;
    }
}

// ---------------------------------------------------------------------------
// kernel_launch
// ---------------------------------------------------------------------------
extern "C" void kernel_launch(void* const* d_in, const int* in_sizes, int n_in,
                              void* d_out, int out_size)
{
    (void)in_sizes; (void)n_in; (void)out_size;
    const float* x  = (const float*)d_in[0];
    const float* Wq = (const float*)d_in[1];
    const float* Wk = (const float*)d_in[2];
    const float* Wv = (const float*)d_in[3];
    const float* Wp = (const float*)d_in[4];
    const float* bp = (const float*)d_in[5];
    float* out = (float*)d_out;

    __nv_bfloat16 *xh, *xl, *Wth, *Wtl, *Qh, *Ql, *Kh, *Kl, *Vh, *Vl,
                  *Vth, *Vtl, *Oh, *Ol, *Ph, *Pl;
    float* S;
    cudaGetSymbolAddress((void**)&xh, g_xh);
    cudaGetSymbolAddress((void**)&xl, g_xl);
    cudaGetSymbolAddress((void**)&Wth, g_Wth);
    cudaGetSymbolAddress((void**)&Wtl, g_Wtl);
    cudaGetSymbolAddress((void**)&Qh, g_Qh);
    cudaGetSymbolAddress((void**)&Ql, g_Ql);
    cudaGetSymbolAddress((void**)&Kh, g_Kh);
    cudaGetSymbolAddress((void**)&Kl, g_Kl);
    cudaGetSymbolAddress((void**)&Vh, g_Vh);
    cudaGetSymbolAddress((void**)&Vl, g_Vl);
    cudaGetSymbolAddress((void**)&Vth, g_Vth);
    cudaGetSymbolAddress((void**)&Vtl, g_Vtl);
    cudaGetSymbolAddress((void**)&Oh, g_Oh);
    cudaGetSymbolAddress((void**)&Ol, g_Ol);
    cudaGetSymbolAddress((void**)&S, g_S);
    cudaGetSymbolAddress((void**)&Ph, g_Ph);
    cudaGetSymbolAddress((void**)&Pl, g_Pl);

    const size_t wstep = (size_t)DIM * DIM;

    cudaFuncSetAttribute(gemm3_kernel<0>, cudaFuncAttributeMaxDynamicSharedMemorySize, SM_TOTAL);
    cudaFuncSetAttribute(gemm3_kernel<1>, cudaFuncAttributeMaxDynamicSharedMemorySize, SM_TOTAL);
    cudaFuncSetAttribute(gemm3_kernel<2>, cudaFuncAttributeMaxDynamicSharedMemorySize, SM_TOTAL);

    // 1) split x into bf16 hi/lo
    split_fp32_kernel<<<(size_t)MTOT * DIM / 1024, 256>>>(x, xh, xl);

    // 2) transpose + split the four weight matrices
    {
        dim3 g(DIM / 32, DIM / 32), b(32, 8);
        transW_kernel<<<g, b>>>(Wq, Wth + 0 * wstep, Wtl + 0 * wstep);
        transW_kernel<<<g, b>>>(Wk, Wth + 1 * wstep, Wtl + 1 * wstep);
        transW_kernel<<<g, b>>>(Wv, Wth + 2 * wstep, Wtl + 2 * wstep);
        transW_kernel<<<g, b>>>(Wp, Wth + 3 * wstep, Wtl + 3 * wstep);
    }

    // 3) Q/K/V projections -> split bf16 outputs
    {
        dim3 g(DIM / 128, MTOT / 128, 1);
        gemm3_kernel<2><<<g, 256, SM_TOTAL>>>(xh, xl, Wth + 0 * wstep, Wtl + 0 * wstep,
                                              nullptr, Qh, Ql, nullptr, DIM, DIM, 0, 0, 0);
        gemm3_kernel<2><<<g, 256, SM_TOTAL>>>(xh, xl, Wth + 1 * wstep, Wtl + 1 * wstep,
                                              nullptr, Kh, Kl, nullptr, DIM, DIM, 0, 0, 0);
        gemm3_kernel<2><<<g, 256, SM_TOTAL>>>(xh, xl, Wth + 2 * wstep, Wtl + 2 * wstep,
                                              nullptr, Vh, Vl, nullptr, DIM, DIM, 0, 0, 0);
    }

    // 4) S = Q @ K^T per batch (fp32 out, raw scores)
    {
        dim3 g(SEQ / 128, SEQ / 128, BATCH);
        gemm3_kernel<0><<<g, 256, SM_TOTAL>>>(Qh, Ql, Kh, Kl,
                                              S, nullptr, nullptr, nullptr,
                                              DIM, SEQ,
                                              (size_t)SEQ * DIM, (size_t)SEQ * DIM,
                                              (size_t)SEQ * SEQ);
    }

    // 5) softmax with scale (log2e folded) -> split bf16 P
    softmax_split_kernel<<<MTOT, 256>>>(S, Ph, Pl, 0.03125f * 1.4426950408889634f);

    // 6) transpose V per batch -> Vt [DIM, SEQ]
    {
        dim3 g(DIM / 32, SEQ / 32, BATCH), b(32, 8);
        transV_kernel<<<g, b>>>(Vh, Vl, Vth, Vtl);
    }

    // 7) O = P @ V per batch -> split bf16 O
    {
        dim3 g(DIM / 128, SEQ / 128, BATCH);
        gemm3_kernel<2><<<g, 256, SM_TOTAL>>>(Ph, Pl, Vth, Vtl,
                                              nullptr, Oh, Ol, nullptr,
                                              SEQ, DIM,
                                              (size_t)SEQ * SEQ, (size_t)DIM * SEQ,
                                              (size_t)SEQ * DIM);
    }

    // 8) out = O @ Wp^T + bp (fp32)
    {
        dim3 g(DIM / 128, MTOT / 128, 1);
        gemm3_kernel<1><<<g, 256, SM_TOTAL>>>(Oh, Ol, Wth + 3 * wstep, Wtl + 3 * wstep,
                                              out, nullptr, nullptr, bp,
                                              DIM, DIM, 0, 0, 0);
    }
}

// round 5
// speedup vs baseline: 1.0064x; 1.0064x over previous
#include <cuda_runtime.h>
#include <cuda_bf16.h>
#include <stdint.h>
#include <math.h>

#define BATCH 8
#define SEQ   2048
#define DIM   1024
#define MTOT  (BATCH * SEQ)

// ---------------------------------------------------------------------------
// Static device scratch (allocation-free contract).
// ---------------------------------------------------------------------------
__device__ __align__(256) __nv_bfloat16 g_xh[(size_t)MTOT * DIM];
__device__ __align__(256) __nv_bfloat16 g_xl[(size_t)MTOT * DIM];
__device__ __align__(256) __nv_bfloat16 g_Wth[4][(size_t)DIM * DIM];
__device__ __align__(256) __nv_bfloat16 g_Wtl[4][(size_t)DIM * DIM];
__device__ __align__(256) __nv_bfloat16 g_Qh[(size_t)MTOT * DIM];
__device__ __align__(256) __nv_bfloat16 g_Ql[(size_t)MTOT * DIM];
__device__ __align__(256) __nv_bfloat16 g_Kh[(size_t)MTOT * DIM];
__device__ __align__(256) __nv_bfloat16 g_Kl[(size_t)MTOT * DIM];
__device__ __align__(256) __nv_bfloat16 g_Vh[(size_t)MTOT * DIM];
__device__ __align__(256) __nv_bfloat16 g_Vl[(size_t)MTOT * DIM];
__device__ __align__(256) __nv_bfloat16 g_Vth[(size_t)MTOT * DIM];
__device__ __align__(256) __nv_bfloat16 g_Vtl[(size_t)MTOT * DIM];
__device__ __align__(256) __nv_bfloat16 g_Oh[(size_t)MTOT * DIM];
__device__ __align__(256) __nv_bfloat16 g_Ol[(size_t)MTOT * DIM];
__device__ __align__(256) float          g_S [(size_t)BATCH * SEQ * SEQ];
__device__ __align__(256) __nv_bfloat16 g_Ph[(size_t)BATCH * SEQ * SEQ];
__device__ __align__(256) __nv_bfloat16 g_Pl[(size_t)BATCH * SEQ * SEQ];

// ---------------------------------------------------------------------------
// Helpers (arch-agnostic PTX only: cp.async / ldmatrix / mma.sync)
// ---------------------------------------------------------------------------
__device__ __forceinline__ uint32_t smem_to_u32(const void* smem_ptr) {
    uint32_t addr;
    asm("{ .reg .u64 tmp; cvta.to.shared.u64 tmp, %1; cvt.u32.u64 %0, tmp; }"
        : "=r"(addr) : "l"(smem_ptr));
    return addr;
}
#define SMEM_SWIZZLE_128B(byte_offset) \
    ((byte_offset) ^ (((byte_offset) >> 3) & 0x70))
#define CP_ASYNC_16(dst_u32, src_ptr) \
    asm volatile("cp.async.cg.shared.global [%0], [%1], 16;" \
                 :: "r"(dst_u32), "l"(src_ptr) : "memory")
#define CP_COMMIT() asm volatile("cp.async.commit_group;" ::: "memory")
#define CP_WAIT(n)  asm volatile("cp.async.wait_group %0;" :: "n"(n) : "memory")

#define LDMATRIX_X4(r0, r1, r2, r3, addr) \
    asm volatile("ldmatrix.sync.aligned.m8n8.x4.shared.b16 {%0,%1,%2,%3}, [%4];" \
                 : "=r"(r0), "=r"(r1), "=r"(r2), "=r"(r3) : "r"(addr))

#define MMA_BF16(c, a, b0, b1) \
    asm volatile("mma.sync.aligned.m16n8k16.row.col.f32.bf16.bf16.f32 " \
                 "{%0,%1,%2,%3}, {%4,%5,%6,%7}, {%8,%9}, {%0,%1,%2,%3};" \
                 : "+f"((c)[0]), "+f"((c)[1]), "+f"((c)[2]), "+f"((c)[3]) \
                 : "r"((a)[0]), "r"((a)[1]), "r"((a)[2]), "r"((a)[3]), \
                   "r"(b0), "r"(b1))

// ---------------------------------------------------------------------------
// GEMM: D[M,N] = A@B^T with 3-term bf16 split folded into K_eff = 3K.
//   A_hi/A_lo: [M,K] K-major bf16 ; B_hi/B_lo: [N,K] K-major bf16
// Tile 128x128, BK=64 bf16 (128B rows, SW128), 3-stage cp.async pipeline,
// 8 warps (4 m x 2 n), warp tile 32x64 via m16n8k16 HMMA.
// NO min-blocks clamp: register pressure must not spill the mainloop.
// EPI: 0 = fp32 out, 1 = fp32 + bias, 2 = split bf16 hi/lo out.
// QKV: if wSel != nullptr, blockIdx.z selects weight set / output (batch=1).
// ---------------------------------------------------------------------------
#define TILE_BYTES 16384            // 128 rows x 128B
#define STAGE_BYTES (2 * TILE_BYTES)
#define STAGES 3
#define SM_TOTAL (STAGES * STAGE_BYTES)   // 98304

template <int EPI, bool MULTI_B>
__global__ void __launch_bounds__(256)
gemm3_kernel(const __nv_bfloat16* __restrict__ Ah, const __nv_bfloat16* __restrict__ Al,
             const __nv_bfloat16* __restrict__ Bh, const __nv_bfloat16* __restrict__ Bl,
             float* __restrict__ Cf,
             __nv_bfloat16* __restrict__ Ch, __nv_bfloat16* __restrict__ Cl,
             __nv_bfloat16* const* __restrict__ multiCh,
             __nv_bfloat16* const* __restrict__ multiCl,
             const float* __restrict__ bias,
             int K, int ldC, size_t sA, size_t sB, size_t sC)
{
    extern __shared__ char smem[];
    const uint32_t smem_u = smem_to_u32(smem);
    const int tid = threadIdx.x;
    const int lane = tid & 31;
    const int wid = tid >> 5;
    const int warp_m = wid & 3;          // 4 warps down M (32 rows each)
    const int warp_n = wid >> 2;         // 2 warps across N (64 cols each)
    const int rowBase = blockIdx.y * 128;
    const int colBase = blockIdx.x * 128;
    const size_t zA = MULTI_B ? 0 : (size_t)blockIdx.z * sA;
    const size_t zB = (size_t)blockIdx.z * sB;
    const size_t zC = MULTI_B ? 0 : (size_t)blockIdx.z * sC;
    __nv_bfloat16* ChSel = MULTI_B ? multiCh[blockIdx.z] : Ch;
    __nv_bfloat16* ClSel = MULTI_B ? multiCl[blockIdx.z] : Cl;

    const int ldr_row0 = tid >> 3;       // rows tid/8, +32, +64, +96
    const int ldr_ch   = tid & 7;

    float acc[2][8][4];
#pragma unroll
    for (int i = 0; i < 2; i++)
#pragma unroll
        for (int j = 0; j < 8; j++)
#pragma unroll
            for (int e = 0; e < 4; e++) acc[i][j][e] = 0.0f;

    const int nk = K >> 6;
    const int nIter = 3 * nk;

    auto issue_load = [&](int i) {
        const int stage = i % STAGES;
        const int seg = i / nk;
        const int kk = (i - seg * nk) << 6;
        const __nv_bfloat16* As = ((seg == 1) ? Al : Ah) + zA;
        const __nv_bfloat16* Bs = ((seg == 2) ? Bl : Bh) + zB;
        const uint32_t aBase = smem_u + stage * STAGE_BYTES;
        const uint32_t bBase = aBase + TILE_BYTES;
#pragma unroll
        for (int p = 0; p < 4; p++) {
            const int row = ldr_row0 + p * 32;
            const uint32_t soff = SMEM_SWIZZLE_128B((uint32_t)row * 128 + ldr_ch * 16);
            CP_ASYNC_16(aBase + soff,
                        As + (size_t)(rowBase + row) * K + kk + ldr_ch * 8);
            CP_ASYNC_16(bBase + soff,
                        Bs + (size_t)(colBase + row) * K + kk + ldr_ch * 8);
        }
    };

    // Prologue: stages 0 and 1 in flight
    issue_load(0); CP_COMMIT();
    issue_load(1); CP_COMMIT();

    for (int i = 0; i < nIter; i++) {
        CP_WAIT(1);                 // stage i ready
        __syncthreads();            // all warps done computing stage (i-1)%3
        if (i + 2 < nIter) issue_load(i + 2);
        CP_COMMIT();                // unconditional: keeps group numbering exact

        const uint32_t aBase = smem_u + (i % STAGES) * STAGE_BYTES;
        const uint32_t bBase = aBase + TILE_BYTES;
#pragma unroll
        for (int ks = 0; ks < 4; ks++) {
            const uint32_t k2 = ks * 32;           // byte offset within 128B row
            uint32_t a[2][4];
#pragma unroll
            for (int fm = 0; fm < 2; fm++) {
                const uint32_t row = warp_m * 32 + fm * 16 + (lane & 15);
                const uint32_t addr = aBase +
                    SMEM_SWIZZLE_128B(row * 128 + k2 + ((lane >> 4) << 4));
                LDMATRIX_X4(a[fm][0], a[fm][1], a[fm][2], a[fm][3], addr);
            }
#pragma unroll
            for (int fn2 = 0; fn2 < 4; fn2++) {
                const uint32_t n = warp_n * 64 + fn2 * 16 + (lane & 7) + ((lane >> 4) << 3);
                const uint32_t addr = bBase +
                    SMEM_SWIZZLE_128B(n * 128 + k2 + (((lane >> 3) & 1) << 4));
                uint32_t b0, b1, b2, b3;
                LDMATRIX_X4(b0, b1, b2, b3, addr);
                MMA_BF16(acc[0][fn2 * 2 + 0], a[0], b0, b1);
                MMA_BF16(acc[0][fn2 * 2 + 1], a[0], b2, b3);
                MMA_BF16(acc[1][fn2 * 2 + 0], a[1], b0, b1);
                MMA_BF16(acc[1][fn2 * 2 + 1], a[1], b2, b3);
            }
        }
    }

    // Epilogue
    const int gid = lane >> 2;
    const int tig = lane & 3;
#pragma unroll
    for (int fm = 0; fm < 2; fm++) {
#pragma unroll
        for (int fn = 0; fn < 8; fn++) {
            const int r0 = rowBase + warp_m * 32 + fm * 16 + gid;
            const int c  = colBase + warp_n * 64 + fn * 8 + tig * 2;
            const float* ac = acc[fm][fn];
            if (EPI == 2) {
                __nv_bfloat162 h0 = __floats2bfloat162_rn(ac[0], ac[1]);
                float2 hf0 = __bfloat1622float2(h0);
                __nv_bfloat162 l0 = __floats2bfloat162_rn(ac[0] - hf0.x, ac[1] - hf0.y);
                __nv_bfloat162 h1 = __floats2bfloat162_rn(ac[2], ac[3]);
                float2 hf1 = __bfloat1622float2(h1);
                __nv_bfloat162 l1 = __floats2bfloat162_rn(ac[2] - hf1.x, ac[3] - hf1.y);
                *(uint32_t*)(ChSel + zC + (size_t)r0 * ldC + c)       = *(uint32_t*)&h0;
                *(uint32_t*)(ClSel + zC + (size_t)r0 * ldC + c)       = *(uint32_t*)&l0;
                *(uint32_t*)(ChSel + zC + (size_t)(r0 + 8) * ldC + c) = *(uint32_t*)&h1;
                *(uint32_t*)(ClSel + zC + (size_t)(r0 + 8) * ldC + c) = *(uint32_t*)&l1;
            } else {
                float2 v0 = make_float2(ac[0], ac[1]);
                float2 v1 = make_float2(ac[2], ac[3]);
                if (EPI == 1) {
                    const float b0 = bias[c], b1 = bias[c + 1];
                    v0.x += b0; v0.y += b1;
                    v1.x += b0; v1.y += b1;
                }
                *(float2*)(Cf + zC + (size_t)r0 * ldC + c)       = v0;
                *(float2*)(Cf + zC + (size_t)(r0 + 8) * ldC + c) = v1;
            }
        }
    }
}

// Device-constant pointer tables for the fused QKV launch
__device__ __nv_bfloat16* g_qkvCh[3];
__device__ __nv_bfloat16* g_qkvCl[3];
__global__ void init_ptrs_kernel() {
    g_qkvCh[0] = g_Qh; g_qkvCh[1] = g_Kh; g_qkvCh[2] = g_Vh;
    g_qkvCl[0] = g_Ql; g_qkvCl[1] = g_Kl; g_qkvCl[2] = g_Vl;
}

// ---------------------------------------------------------------------------
// fp32 -> bf16 hi/lo split (elementwise)
// ---------------------------------------------------------------------------
__global__ void __launch_bounds__(256)
split_fp32_kernel(const float* __restrict__ x,
                  __nv_bfloat16* __restrict__ h, __nv_bfloat16* __restrict__ l)
{
    size_t i = ((size_t)blockIdx.x * 256 + threadIdx.x) * 4;
    float4 v = *(const float4*)(x + i);
    float vv[4] = {v.x, v.y, v.z, v.w};
    __nv_bfloat16 hh[4], ll[4];
#pragma unroll
    for (int j = 0; j < 4; j++) {
        hh[j] = __float2bfloat16(vv[j]);
        ll[j] = __float2bfloat16(vv[j] - __bfloat162float(hh[j]));
    }
    *(uint2*)(h + i) = *(uint2*)hh;
    *(uint2*)(l + i) = *(uint2*)ll;
}

// ---------------------------------------------------------------------------
// Transpose fp32 W [DIM,DIM] -> split bf16 Wt hi/lo (Wt[e,d] = W[d,e])
// ---------------------------------------------------------------------------
__global__ void __launch_bounds__(256)
transW_kernel(const float* __restrict__ W,
              __nv_bfloat16* __restrict__ th, __nv_bfloat16* __restrict__ tl)
{
    __shared__ float t[32][33];
    const int tx = threadIdx.x, ty = threadIdx.y;
    const int x = blockIdx.x * 32 + tx;
    const int y0 = blockIdx.y * 32;
#pragma unroll
    for (int p = 0; p < 4; p++)
        t[ty + 8 * p][tx] = W[(size_t)(y0 + ty + 8 * p) * DIM + x];
    __syncthreads();
    const int ox = blockIdx.y * 32 + tx;
    const int oy0 = blockIdx.x * 32;
#pragma unroll
    for (int p = 0; p < 4; p++) {
        float v = t[tx][ty + 8 * p];
        __nv_bfloat16 h = __float2bfloat16(v);
        __nv_bfloat16 l = __float2bfloat16(v - __bfloat162float(h));
        th[(size_t)(oy0 + ty + 8 * p) * DIM + ox] = h;
        tl[(size_t)(oy0 + ty + 8 * p) * DIM + ox] = l;
    }
}

// ---------------------------------------------------------------------------
// Transpose bf16 pair per batch: V [SEQ,DIM] -> Vt [DIM,SEQ]
// ---------------------------------------------------------------------------
__global__ void __launch_bounds__(256)
transV_kernel(const __nv_bfloat16* __restrict__ ih, const __nv_bfloat16* __restrict__ il,
              __nv_bfloat16* __restrict__ oh, __nv_bfloat16* __restrict__ ol)
{
    __shared__ __nv_bfloat16 t0[32][33];
    __shared__ __nv_bfloat16 t1[32][33];
    const size_t zin = (size_t)blockIdx.z * SEQ * DIM;
    const int tx = threadIdx.x, ty = threadIdx.y;
    const int x = blockIdx.x * 32 + tx;
    const int y0 = blockIdx.y * 32;
#pragma unroll
    for (int p = 0; p < 4; p++) {
        t0[ty + 8 * p][tx] = ih[zin + (size_t)(y0 + ty + 8 * p) * DIM + x];
        t1[ty + 8 * p][tx] = il[zin + (size_t)(y0 + ty + 8 * p) * DIM + x];
    }
    __syncthreads();
    const int ox = blockIdx.y * 32 + tx;
    const int oy0 = blockIdx.x * 32;
#pragma unroll
    for (int p = 0; p < 4; p++) {
        oh[zin + (size_t)(oy0 + ty + 8 * p) * SEQ + ox] = t0[tx][ty + 8 * p];
        ol[zin + (size_t)(oy0 + ty + 8 * p) * SEQ + ox] = t1[tx][ty + 8 * p];
    }
}

// ---------------------------------------------------------------------------
// Row softmax (SEQ=2048 cols) in log2 domain; emits split-bf16 P
// ---------------------------------------------------------------------------
__global__ void __launch_bounds__(256)
softmax_split_kernel(const float* __restrict__ S,
                     __nv_bfloat16* __restrict__ Ph, __nv_bfloat16* __restrict__ Pl,
                     float scale_log2e)
{
    const size_t row = blockIdx.x;
    const float* p = S + row * SEQ;
    const int tid = threadIdx.x;

    float vals[8];
    float lmax = -INFINITY;
#pragma unroll
    for (int i = 0; i < 8; i++) {
        float v = p[tid + i * 256] * scale_log2e;
        vals[i] = v;
        lmax = fmaxf(lmax, v);
    }
    __shared__ float red[8];
#pragma unroll
    for (int o = 16; o > 0; o >>= 1)
        lmax = fmaxf(lmax, __shfl_xor_sync(0xffffffffu, lmax, o));
    if ((tid & 31) == 0) red[tid >> 5] = lmax;
    __syncthreads();
    float m = red[0];
#pragma unroll
    for (int w = 1; w < 8; w++) m = fmaxf(m, red[w]);
    __syncthreads();

    float lsum = 0.0f;
#pragma unroll
    for (int i = 0; i < 8; i++) {
        vals[i] = exp2f(vals[i] - m);
        lsum += vals[i];
    }
#pragma unroll
    for (int o = 16; o > 0; o >>= 1)
        lsum += __shfl_xor_sync(0xffffffffu, lsum, o);
    if ((tid & 31) == 0) red[tid >> 5] = lsum;
    __syncthreads();
    float tot = 0.0f;
#pragma unroll
    for (int w = 0; w < 8; w++) tot += red[w];
    const float rinv = 1.0f / tot;

#pragma unroll
    for (int i = 0; i < 8; i++) {
        float v = vals[i] * rinv;
        __nv_bfloat16 h = __float2bfloat16(v);
        __nv_bfloat16 l = __float2bfloat16(v - __bfloat162float(h));
        Ph[row * SEQ + tid + i * 256] = h;
        Pl[row * SEQ + tid + i * 256] = l;
    }
}

// ---------------------------------------------------------------------------
// kernel_launch
// ---------------------------------------------------------------------------
extern "C" void kernel_launch(void* const* d_in, const int* in_sizes, int n_in,
                              void* d_out, int out_size)
{
    (void)in_sizes; (void)n_in; (void)out_size;
    const float* x  = (const float*)d_in[0];
    const float* Wq = (const float*)d_in[1];
    const float* Wk = (const float*)d_in[2];
    const float* Wv = (const float*)d_in[3];
    const float* Wp = (const float*)d_in[4];
    const float* bp = (const float*)d_in[5];
    float* out = (float*)d_out;

    __nv_bfloat16 *xh, *xl, *Wth, *Wtl, *Qh, *Ql, *Kh, *Kl, *Vh, *Vl,
                  *Vth, *Vtl, *Oh, *Ol, *Ph, *Pl;
    float* S;
    __nv_bfloat16 **qkvCh, **qkvCl;
    cudaGetSymbolAddress((void**)&xh, g_xh);
    cudaGetSymbolAddress((void**)&xl, g_xl);
    cudaGetSymbolAddress((void**)&Wth, g_Wth);
    cudaGetSymbolAddress((void**)&Wtl, g_Wtl);
    cudaGetSymbolAddress((void**)&Qh, g_Qh);
    cudaGetSymbolAddress((void**)&Ql, g_Ql);
    cudaGetSymbolAddress((void**)&Kh, g_Kh);
    cudaGetSymbolAddress((void**)&Kl, g_Kl);
    cudaGetSymbolAddress((void**)&Vh, g_Vh);
    cudaGetSymbolAddress((void**)&Vl, g_Vl);
    cudaGetSymbolAddress((void**)&Vth, g_Vth);
    cudaGetSymbolAddress((void**)&Vtl, g_Vtl);
    cudaGetSymbolAddress((void**)&Oh, g_Oh);
    cudaGetSymbolAddress((void**)&Ol, g_Ol);
    cudaGetSymbolAddress((void**)&S, g_S);
    cudaGetSymbolAddress((void**)&Ph, g_Ph);
    cudaGetSymbolAddress((void**)&Pl, g_Pl);
    cudaGetSymbolAddress((void**)&qkvCh, g_qkvCh);
    cudaGetSymbolAddress((void**)&qkvCl, g_qkvCl);

    const size_t wstep = (size_t)DIM * DIM;

    cudaFuncSetAttribute(gemm3_kernel<0, false>, cudaFuncAttributeMaxDynamicSharedMemorySize, SM_TOTAL);
    cudaFuncSetAttribute(gemm3_kernel<1, false>, cudaFuncAttributeMaxDynamicSharedMemorySize, SM_TOTAL);
    cudaFuncSetAttribute(gemm3_kernel<2, false>, cudaFuncAttributeMaxDynamicSharedMemorySize, SM_TOTAL);
    cudaFuncSetAttribute(gemm3_kernel<2, true>,  cudaFuncAttributeMaxDynamicSharedMemorySize, SM_TOTAL);

    // Prep (order chosen so ncu -s window lands on a GEMM):
    init_ptrs_kernel<<<1, 1>>>();
    {
        dim3 g(DIM / 32, DIM / 32), b(32, 8);
        transW_kernel<<<g, b>>>(Wq, Wth + 0 * wstep, Wtl + 0 * wstep);
        transW_kernel<<<g, b>>>(Wk, Wth + 1 * wstep, Wtl + 1 * wstep);
        transW_kernel<<<g, b>>>(Wv, Wth + 2 * wstep, Wtl + 2 * wstep);
        transW_kernel<<<g, b>>>(Wp, Wth + 3 * wstep, Wtl + 3 * wstep);
    }
    split_fp32_kernel<<<(size_t)MTOT * DIM / 1024, 256>>>(x, xh, xl);

    // 1) Q/K/V projections fused in one launch (z selects weight/output)
    {
        dim3 g(DIM / 128, MTOT / 128, 3);
        gemm3_kernel<2, true><<<g, 256, SM_TOTAL>>>(
            xh, xl, Wth, Wtl,
            nullptr, nullptr, nullptr, qkvCh, qkvCl, nullptr,
            DIM, DIM, 0, wstep, 0);
    }

    // 2) S = Q @ K^T per batch (fp32 out, raw scores)
    {
        dim3 g(SEQ / 128, SEQ / 128, BATCH);
        gemm3_kernel<0, false><<<g, 256, SM_TOTAL>>>(
            Qh, Ql, Kh, Kl,
            S, nullptr, nullptr, nullptr, nullptr, nullptr,
            DIM, SEQ,
            (size_t)SEQ * DIM, (size_t)SEQ * DIM, (size_t)SEQ * SEQ);
    }

    // 3) softmax (log2-domain) -> split bf16 P
    softmax_split_kernel<<<MTOT, 256>>>(S, Ph, Pl, 0.03125f * 1.4426950408889634f);

    // 4) transpose V per batch -> Vt [DIM, SEQ]
    {
        dim3 g(DIM / 32, SEQ / 32, BATCH), b(32, 8);
        transV_kernel<<<g, b>>>(Vh, Vl, Vth, Vtl);
    }

    // 5) O = P @ V per batch -> split bf16 O
    {
        dim3 g(DIM / 128, SEQ / 128, BATCH);
        gemm3_kernel<2, false><<<g, 256, SM_TOTAL>>>(
            Ph, Pl, Vth, Vtl,
            nullptr, Oh, Ol, nullptr, nullptr, nullptr,
            SEQ, DIM,
            (size_t)SEQ * SEQ, (size_t)DIM * SEQ, (size_t)SEQ * DIM);
    }

    // 6) out = O @ Wp^T + bp (fp32)
    {
        dim3 g(DIM / 128, MTOT / 128, 1);
        gemm3_kernel<1, false><<<g, 256, SM_TOTAL>>>(
            Oh, Ol, Wth + 3 * wstep, Wtl + 3 * wstep,
            out, nullptr, nullptr, nullptr, nullptr, bp,
            DIM, DIM, 0, 0, 0);
    }
}

// round 6
// speedup vs baseline: 1.0547x; 1.0479x over previous
#include <cuda_runtime.h>
#include <cuda_bf16.h>
#include <stdint.h>
#include <math.h>

#define BATCH 8
#define SEQ   2048
#define DIM   1024
#define MTOT  (BATCH * SEQ)

// ---------------------------------------------------------------------------
// Static device scratch (allocation-free contract).
// ---------------------------------------------------------------------------
__device__ __align__(256) __nv_bfloat16 g_xh[(size_t)MTOT * DIM];
__device__ __align__(256) __nv_bfloat16 g_xl[(size_t)MTOT * DIM];
__device__ __align__(256) __nv_bfloat16 g_Wth[4][(size_t)DIM * DIM];
__device__ __align__(256) __nv_bfloat16 g_Wtl[4][(size_t)DIM * DIM];
__device__ __align__(256) __nv_bfloat16 g_Qh[(size_t)MTOT * DIM];
__device__ __align__(256) __nv_bfloat16 g_Ql[(size_t)MTOT * DIM];
__device__ __align__(256) __nv_bfloat16 g_Kh[(size_t)MTOT * DIM];
__device__ __align__(256) __nv_bfloat16 g_Kl[(size_t)MTOT * DIM];
__device__ __align__(256) __nv_bfloat16 g_Vh[(size_t)MTOT * DIM];
__device__ __align__(256) __nv_bfloat16 g_Vl[(size_t)MTOT * DIM];
__device__ __align__(256) __nv_bfloat16 g_Vth[(size_t)MTOT * DIM];
__device__ __align__(256) __nv_bfloat16 g_Vtl[(size_t)MTOT * DIM];
__device__ __align__(256) __nv_bfloat16 g_Oh[(size_t)MTOT * DIM];
__device__ __align__(256) __nv_bfloat16 g_Ol[(size_t)MTOT * DIM];
__device__ __align__(256) float          g_S [(size_t)BATCH * SEQ * SEQ];
__device__ __align__(256) __nv_bfloat16 g_Ph[(size_t)BATCH * SEQ * SEQ];
__device__ __align__(256) __nv_bfloat16 g_Pl[(size_t)BATCH * SEQ * SEQ];

// ---------------------------------------------------------------------------
// Helpers (arch-agnostic PTX only: cp.async / ldmatrix / mma.sync)
// ---------------------------------------------------------------------------
__device__ __forceinline__ uint32_t smem_to_u32(const void* smem_ptr) {
    uint32_t addr;
    asm("{ .reg .u64 tmp; cvta.to.shared.u64 tmp, %1; cvt.u32.u64 %0, tmp; }"
        : "=r"(addr) : "l"(smem_ptr));
    return addr;
}
#define SMEM_SWIZZLE_128B(byte_offset) \
    ((byte_offset) ^ (((byte_offset) >> 3) & 0x70))
#define CP_ASYNC_16(dst_u32, src_ptr) \
    asm volatile("cp.async.cg.shared.global [%0], [%1], 16;" \
                 :: "r"(dst_u32), "l"(src_ptr) : "memory")
#define CP_COMMIT() asm volatile("cp.async.commit_group;" ::: "memory")
#define CP_WAIT(n)  asm volatile("cp.async.wait_group %0;" :: "n"(n) : "memory")

#define LDMATRIX_X4(r0, r1, r2, r3, addr) \
    asm volatile("ldmatrix.sync.aligned.m8n8.x4.shared.b16 {%0,%1,%2,%3}, [%4];" \
                 : "=r"(r0), "=r"(r1), "=r"(r2), "=r"(r3) : "r"(addr))

#define MMA_BF16(c, a, b0, b1) \
    asm volatile("mma.sync.aligned.m16n8k16.row.col.f32.bf16.bf16.f32 " \
                 "{%0,%1,%2,%3}, {%4,%5,%6,%7}, {%8,%9}, {%0,%1,%2,%3};" \
                 : "+f"((c)[0]), "+f"((c)[1]), "+f"((c)[2]), "+f"((c)[3]) \
                 : "r"((a)[0]), "r"((a)[1]), "r"((a)[2]), "r"((a)[3]), \
                   "r"(b0), "r"(b1))

// ---------------------------------------------------------------------------
// GEMM: D[M,N] = A@B^T with 3-term bf16 split folded into K_eff = 3K.
// Tile 128x128, BK=64 bf16 (128B rows, SW128), 2-stage cp.async double buffer
// (round-3 proven structure), 8 warps (4m x 2n), warp tile 32x64 m16n8k16.
// EPI: 0 = fp32 out, 1 = fp32 + bias, 2 = split bf16 hi/lo out.
// MULTI_B: blockIdx.z selects weight set / output via pointer tables.
// ---------------------------------------------------------------------------
#define TILE_BYTES 16384            // 128 rows x 128B
#define STAGE_BYTES (2 * TILE_BYTES)
#define SM_TOTAL (2 * STAGE_BYTES)  // 65536

template <int EPI, bool MULTI_B>
__global__ void __launch_bounds__(256)
gemm3_kernel(const __nv_bfloat16* __restrict__ Ah, const __nv_bfloat16* __restrict__ Al,
             const __nv_bfloat16* __restrict__ Bh, const __nv_bfloat16* __restrict__ Bl,
             float* __restrict__ Cf,
             __nv_bfloat16* __restrict__ Ch, __nv_bfloat16* __restrict__ Cl,
             __nv_bfloat16* const* __restrict__ multiCh,
             __nv_bfloat16* const* __restrict__ multiCl,
             const float* __restrict__ bias,
             int K, int ldC, size_t sA, size_t sB, size_t sC)
{
    extern __shared__ char smem[];
    const uint32_t smem_u = smem_to_u32(smem);
    const int tid = threadIdx.x;
    const int lane = tid & 31;
    const int wid = tid >> 5;
    const int warp_m = wid & 3;
    const int warp_n = wid >> 2;
    const int rowBase = blockIdx.y * 128;
    const int colBase = blockIdx.x * 128;
    const size_t zA = MULTI_B ? 0 : (size_t)blockIdx.z * sA;
    const size_t zB = (size_t)blockIdx.z * sB;
    const size_t zC = MULTI_B ? 0 : (size_t)blockIdx.z * sC;
    __nv_bfloat16* ChSel = MULTI_B ? multiCh[blockIdx.z] : Ch;
    __nv_bfloat16* ClSel = MULTI_B ? multiCl[blockIdx.z] : Cl;

    const int ldr_row0 = tid >> 3;
    const int ldr_ch   = tid & 7;

    float acc[2][8][4];
#pragma unroll
    for (int i = 0; i < 2; i++)
#pragma unroll
        for (int j = 0; j < 8; j++)
#pragma unroll
            for (int e = 0; e < 4; e++) acc[i][j][e] = 0.0f;

    const int nk = K >> 6;
    const int nIter = 3 * nk;

    auto issue_load = [&](int i, int stage) {
        const int seg = i / nk;
        const int kk = (i - seg * nk) << 6;
        const __nv_bfloat16* As = ((seg == 1) ? Al : Ah) + zA;
        const __nv_bfloat16* Bs = ((seg == 2) ? Bl : Bh) + zB;
        const uint32_t aBase = smem_u + stage * STAGE_BYTES;
        const uint32_t bBase = aBase + TILE_BYTES;
#pragma unroll
        for (int p = 0; p < 4; p++) {
            const int row = ldr_row0 + p * 32;
            const uint32_t soff = SMEM_SWIZZLE_128B((uint32_t)row * 128 + ldr_ch * 16);
            CP_ASYNC_16(aBase + soff,
                        As + (size_t)(rowBase + row) * K + kk + ldr_ch * 8);
            CP_ASYNC_16(bBase + soff,
                        Bs + (size_t)(colBase + row) * K + kk + ldr_ch * 8);
        }
        CP_COMMIT();
    };

    issue_load(0, 0);

    for (int i = 0; i < nIter; i++) {
        const int stage = i & 1;
        if (i + 1 < nIter) {
            issue_load(i + 1, (i + 1) & 1);
            CP_WAIT(1);
        } else {
            CP_WAIT(0);
        }
        __syncthreads();

        const uint32_t aBase = smem_u + stage * STAGE_BYTES;
        const uint32_t bBase = aBase + TILE_BYTES;
#pragma unroll
        for (int ks = 0; ks < 4; ks++) {
            const uint32_t k2 = ks * 32;
            uint32_t a[2][4];
#pragma unroll
            for (int fm = 0; fm < 2; fm++) {
                const uint32_t row = warp_m * 32 + fm * 16 + (lane & 15);
                const uint32_t addr = aBase +
                    SMEM_SWIZZLE_128B(row * 128 + k2 + ((lane >> 4) << 4));
                LDMATRIX_X4(a[fm][0], a[fm][1], a[fm][2], a[fm][3], addr);
            }
#pragma unroll
            for (int fn2 = 0; fn2 < 4; fn2++) {
                const uint32_t n = warp_n * 64 + fn2 * 16 + (lane & 7) + ((lane >> 4) << 3);
                const uint32_t addr = bBase +
                    SMEM_SWIZZLE_128B(n * 128 + k2 + (((lane >> 3) & 1) << 4));
                uint32_t b0, b1, b2, b3;
                LDMATRIX_X4(b0, b1, b2, b3, addr);
                MMA_BF16(acc[0][fn2 * 2 + 0], a[0], b0, b1);
                MMA_BF16(acc[0][fn2 * 2 + 1], a[0], b2, b3);
                MMA_BF16(acc[1][fn2 * 2 + 0], a[1], b0, b1);
                MMA_BF16(acc[1][fn2 * 2 + 1], a[1], b2, b3);
            }
        }
        __syncthreads();
    }

    // Epilogue
    const int gid = lane >> 2;
    const int tig = lane & 3;
#pragma unroll
    for (int fm = 0; fm < 2; fm++) {
#pragma unroll
        for (int fn = 0; fn < 8; fn++) {
            const int r0 = rowBase + warp_m * 32 + fm * 16 + gid;
            const int c  = colBase + warp_n * 64 + fn * 8 + tig * 2;
            const float* ac = acc[fm][fn];
            if (EPI == 2) {
                __nv_bfloat162 h0 = __floats2bfloat162_rn(ac[0], ac[1]);
                float2 hf0 = __bfloat1622float2(h0);
                __nv_bfloat162 l0 = __floats2bfloat162_rn(ac[0] - hf0.x, ac[1] - hf0.y);
                __nv_bfloat162 h1 = __floats2bfloat162_rn(ac[2], ac[3]);
                float2 hf1 = __bfloat1622float2(h1);
                __nv_bfloat162 l1 = __floats2bfloat162_rn(ac[2] - hf1.x, ac[3] - hf1.y);
                *(uint32_t*)(ChSel + zC + (size_t)r0 * ldC + c)       = *(uint32_t*)&h0;
                *(uint32_t*)(ClSel + zC + (size_t)r0 * ldC + c)       = *(uint32_t*)&l0;
                *(uint32_t*)(ChSel + zC + (size_t)(r0 + 8) * ldC + c) = *(uint32_t*)&h1;
                *(uint32_t*)(ClSel + zC + (size_t)(r0 + 8) * ldC + c) = *(uint32_t*)&l1;
            } else {
                float2 v0 = make_float2(ac[0], ac[1]);
                float2 v1 = make_float2(ac[2], ac[3]);
                if (EPI == 1) {
                    const float b0 = bias[c], b1 = bias[c + 1];
                    v0.x += b0; v0.y += b1;
                    v1.x += b0; v1.y += b1;
                }
                *(float2*)(Cf + zC + (size_t)r0 * ldC + c)       = v0;
                *(float2*)(Cf + zC + (size_t)(r0 + 8) * ldC + c) = v1;
            }
        }
    }
}

// Pointer tables (device) for fused multi-output launches
__device__ __nv_bfloat16* g_qkvCh[3];
__device__ __nv_bfloat16* g_qkvCl[3];
__device__ const float*   g_wIn[4];
__global__ void init_ptrs_kernel(const float* Wq, const float* Wk,
                                 const float* Wv, const float* Wp) {
    g_qkvCh[0] = g_Qh; g_qkvCh[1] = g_Kh; g_qkvCh[2] = g_Vh;
    g_qkvCl[0] = g_Ql; g_qkvCl[1] = g_Kl; g_qkvCl[2] = g_Vl;
    g_wIn[0] = Wq; g_wIn[1] = Wk; g_wIn[2] = Wv; g_wIn[3] = Wp;
}

// ---------------------------------------------------------------------------
// fp32 -> bf16 hi/lo split (elementwise)
// ---------------------------------------------------------------------------
__global__ void __launch_bounds__(256)
split_fp32_kernel(const float* __restrict__ x,
                  __nv_bfloat16* __restrict__ h, __nv_bfloat16* __restrict__ l)
{
    size_t i = ((size_t)blockIdx.x * 256 + threadIdx.x) * 4;
    float4 v = *(const float4*)(x + i);
    float vv[4] = {v.x, v.y, v.z, v.w};
    __nv_bfloat16 hh[4], ll[4];
#pragma unroll
    for (int j = 0; j < 4; j++) {
        hh[j] = __float2bfloat16(vv[j]);
        ll[j] = __float2bfloat16(vv[j] - __bfloat162float(hh[j]));
    }
    *(uint2*)(h + i) = *(uint2*)hh;
    *(uint2*)(l + i) = *(uint2*)ll;
}

// ---------------------------------------------------------------------------
// Transpose + split ALL FOUR weight matrices in one launch (z selects).
// ---------------------------------------------------------------------------
__global__ void __launch_bounds__(256)
transW_all_kernel(__nv_bfloat16* __restrict__ thB, __nv_bfloat16* __restrict__ tlB)
{
    const float* W = g_wIn[blockIdx.z];
    __nv_bfloat16* th = thB + (size_t)blockIdx.z * DIM * DIM;
    __nv_bfloat16* tl = tlB + (size_t)blockIdx.z * DIM * DIM;
    __shared__ float t[32][33];
    const int tx = threadIdx.x, ty = threadIdx.y;
    const int x = blockIdx.x * 32 + tx;
    const int y0 = blockIdx.y * 32;
#pragma unroll
    for (int p = 0; p < 4; p++)
        t[ty + 8 * p][tx] = W[(size_t)(y0 + ty + 8 * p) * DIM + x];
    __syncthreads();
    const int ox = blockIdx.y * 32 + tx;
    const int oy0 = blockIdx.x * 32;
#pragma unroll
    for (int p = 0; p < 4; p++) {
        float v = t[tx][ty + 8 * p];
        __nv_bfloat16 h = __float2bfloat16(v);
        __nv_bfloat16 l = __float2bfloat16(v - __bfloat162float(h));
        th[(size_t)(oy0 + ty + 8 * p) * DIM + ox] = h;
        tl[(size_t)(oy0 + ty + 8 * p) * DIM + ox] = l;
    }
}

// ---------------------------------------------------------------------------
// Transpose bf16 pair per batch: V [SEQ,DIM] -> Vt [DIM,SEQ]
// ---------------------------------------------------------------------------
__global__ void __launch_bounds__(256)
transV_kernel(const __nv_bfloat16* __restrict__ ih, const __nv_bfloat16* __restrict__ il,
              __nv_bfloat16* __restrict__ oh, __nv_bfloat16* __restrict__ ol)
{
    __shared__ __nv_bfloat16 t0[32][33];
    __shared__ __nv_bfloat16 t1[32][33];
    const size_t zin = (size_t)blockIdx.z * SEQ * DIM;
    const int tx = threadIdx.x, ty = threadIdx.y;
    const int x = blockIdx.x * 32 + tx;
    const int y0 = blockIdx.y * 32;
#pragma unroll
    for (int p = 0; p < 4; p++) {
        t0[ty + 8 * p][tx] = ih[zin + (size_t)(y0 + ty + 8 * p) * DIM + x];
        t1[ty + 8 * p][tx] = il[zin + (size_t)(y0 + ty + 8 * p) * DIM + x];
    }
    __syncthreads();
    const int ox = blockIdx.y * 32 + tx;
    const int oy0 = blockIdx.x * 32;
#pragma unroll
    for (int p = 0; p < 4; p++) {
        oh[zin + (size_t)(oy0 + ty + 8 * p) * SEQ + ox] = t0[tx][ty + 8 * p];
        ol[zin + (size_t)(oy0 + ty + 8 * p) * SEQ + ox] = t1[tx][ty + 8 * p];
    }
}

// ---------------------------------------------------------------------------
// Row softmax (SEQ=2048 cols) in log2 domain; emits split-bf16 P
// ---------------------------------------------------------------------------
__global__ void __launch_bounds__(256)
softmax_split_kernel(const float* __restrict__ S,
                     __nv_bfloat16* __restrict__ Ph, __nv_bfloat16* __restrict__ Pl,
                     float scale_log2e)
{
    const size_t row = blockIdx.x;
    const float* p = S + row * SEQ;
    const int tid = threadIdx.x;

    float vals[8];
    float lmax = -INFINITY;
#pragma unroll
    for (int i = 0; i < 8; i++) {
        float v = p[tid + i * 256] * scale_log2e;
        vals[i] = v;
        lmax = fmaxf(lmax, v);
    }
    __shared__ float red[8];
#pragma unroll
    for (int o = 16; o > 0; o >>= 1)
        lmax = fmaxf(lmax, __shfl_xor_sync(0xffffffffu, lmax, o));
    if ((tid & 31) == 0) red[tid >> 5] = lmax;
    __syncthreads();
    float m = red[0];
#pragma unroll
    for (int w = 1; w < 8; w++) m = fmaxf(m, red[w]);
    __syncthreads();

    float lsum = 0.0f;
#pragma unroll
    for (int i = 0; i < 8; i++) {
        vals[i] = exp2f(vals[i] - m);
        lsum += vals[i];
    }
#pragma unroll
    for (int o = 16; o > 0; o >>= 1)
        lsum += __shfl_xor_sync(0xffffffffu, lsum, o);
    if ((tid & 31) == 0) red[tid >> 5] = lsum;
    __syncthreads();
    float tot = 0.0f;
#pragma unroll
    for (int w = 0; w < 8; w++) tot += red[w];
    const float rinv = 1.0f / tot;

#pragma unroll
    for (int i = 0; i < 8; i++) {
        float v = vals[i] * rinv;
        __nv_bfloat16 h = __float2bfloat16(v);
        __nv_bfloat16 l = __float2bfloat16(v - __bfloat162float(h));
        Ph[row * SEQ + tid + i * 256] = h;
        Pl[row * SEQ + tid + i * 256] = l;
    }
}

// ---------------------------------------------------------------------------
// kernel_launch
// ---------------------------------------------------------------------------
extern "C" void kernel_launch(void* const* d_in, const int* in_sizes, int n_in,
                              void* d_out, int out_size)
{
    (void)in_sizes; (void)n_in; (void)out_size;
    const float* x  = (const float*)d_in[0];
    const float* Wq = (const float*)d_in[1];
    const float* Wk = (const float*)d_in[2];
    const float* Wv = (const float*)d_in[3];
    const float* Wp = (const float*)d_in[4];
    const float* bp = (const float*)d_in[5];
    float* out = (float*)d_out;

    __nv_bfloat16 *xh, *xl, *Wth, *Wtl, *Qh, *Ql, *Kh, *Kl, *Vh, *Vl,
                  *Vth, *Vtl, *Oh, *Ol, *Ph, *Pl;
    float* S;
    __nv_bfloat16 **qkvCh, **qkvCl;
    cudaGetSymbolAddress((void**)&xh, g_xh);
    cudaGetSymbolAddress((void**)&xl, g_xl);
    cudaGetSymbolAddress((void**)&Wth, g_Wth);
    cudaGetSymbolAddress((void**)&Wtl, g_Wtl);
    cudaGetSymbolAddress((void**)&Qh, g_Qh);
    cudaGetSymbolAddress((void**)&Ql, g_Ql);
    cudaGetSymbolAddress((void**)&Kh, g_Kh);
    cudaGetSymbolAddress((void**)&Kl, g_Kl);
    cudaGetSymbolAddress((void**)&Vh, g_Vh);
    cudaGetSymbolAddress((void**)&Vl, g_Vl);
    cudaGetSymbolAddress((void**)&Vth, g_Vth);
    cudaGetSymbolAddress((void**)&Vtl, g_Vtl);
    cudaGetSymbolAddress((void**)&Oh, g_Oh);
    cudaGetSymbolAddress((void**)&Ol, g_Ol);
    cudaGetSymbolAddress((void**)&S, g_S);
    cudaGetSymbolAddress((void**)&Ph, g_Ph);
    cudaGetSymbolAddress((void**)&Pl, g_Pl);
    cudaGetSymbolAddress((void**)&qkvCh, g_qkvCh);
    cudaGetSymbolAddress((void**)&qkvCl, g_qkvCl);

    const size_t wstep = (size_t)DIM * DIM;

    cudaFuncSetAttribute(gemm3_kernel<0, false>, cudaFuncAttributeMaxDynamicSharedMemorySize, SM_TOTAL);
    cudaFuncSetAttribute(gemm3_kernel<1, false>, cudaFuncAttributeMaxDynamicSharedMemorySize, SM_TOTAL);
    cudaFuncSetAttribute(gemm3_kernel<2, false>, cudaFuncAttributeMaxDynamicSharedMemorySize, SM_TOTAL);
    cudaFuncSetAttribute(gemm3_kernel<2, true>,  cudaFuncAttributeMaxDynamicSharedMemorySize, SM_TOTAL);

    // Launch 1: pointer tables
    init_ptrs_kernel<<<1, 1>>>(Wq, Wk, Wv, Wp);

    // Launch 2: transpose + split all four weights
    {
        dim3 g(DIM / 32, DIM / 32, 4), b(32, 8);
        transW_all_kernel<<<g, b>>>(Wth, Wtl);
    }

    // Launch 3: split x
    split_fp32_kernel<<<(size_t)MTOT * DIM / 1024, 256>>>(x, xh, xl);

    // Launch 4: fused Q/K/V projections
    {
        dim3 g(DIM / 128, MTOT / 128, 3);
        gemm3_kernel<2, true><<<g, 256, SM_TOTAL>>>(
            xh, xl, Wth, Wtl,
            nullptr, nullptr, nullptr, qkvCh, qkvCl, nullptr,
            DIM, DIM, 0, wstep, 0);
    }

    // Launch 5 (ncu target): S = Q @ K^T per batch
    {
        dim3 g(SEQ / 128, SEQ / 128, BATCH);
        gemm3_kernel<0, false><<<g, 256, SM_TOTAL>>>(
            Qh, Ql, Kh, Kl,
            S, nullptr, nullptr, nullptr, nullptr, nullptr,
            DIM, SEQ,
            (size_t)SEQ * DIM, (size_t)SEQ * DIM, (size_t)SEQ * SEQ);
    }

    // softmax (log2 domain) -> split bf16 P
    softmax_split_kernel<<<MTOT, 256>>>(S, Ph, Pl, 0.03125f * 1.4426950408889634f);

    // transpose V per batch -> Vt [DIM, SEQ]
    {
        dim3 g(DIM / 32, SEQ / 32, BATCH), b(32, 8);
        transV_kernel<<<g, b>>>(Vh, Vl, Vth, Vtl);
    }

    // O = P @ V per batch -> split bf16 O
    {
        dim3 g(DIM / 128, SEQ / 128, BATCH);
        gemm3_kernel<2, false><<<g, 256, SM_TOTAL>>>(
            Ph, Pl, Vth, Vtl,
            nullptr, Oh, Ol, nullptr, nullptr, nullptr,
            SEQ, DIM,
            (size_t)SEQ * SEQ, (size_t)DIM * SEQ, (size_t)SEQ * DIM);
    }

    // out = O @ Wp^T + bp (fp32)
    {
        dim3 g(DIM / 128, MTOT / 128, 1);
        gemm3_kernel<1, false><<<g, 256, SM_TOTAL>>>(
            Oh, Ol, Wth + 3 * wstep, Wtl + 3 * wstep,
            out, nullptr, nullptr, nullptr, nullptr, bp,
            DIM, DIM, 0, 0, 0);
    }
}

// round 7
// speedup vs baseline: 1.0569x; 1.0021x over previous
#include <cuda_runtime.h>
#include <cuda_bf16.h>
#include <stdint.h>
#include <math.h>

#define BATCH 8
#define SEQ   2048
#define DIM   1024
#define MTOT  (BATCH * SEQ)

// ---------------------------------------------------------------------------
// Static device scratch (allocation-free contract).
// ---------------------------------------------------------------------------
__device__ __align__(256) __nv_bfloat16 g_xh[(size_t)MTOT * DIM];
__device__ __align__(256) __nv_bfloat16 g_xl[(size_t)MTOT * DIM];
__device__ __align__(256) __nv_bfloat16 g_Wth[4][(size_t)DIM * DIM];
__device__ __align__(256) __nv_bfloat16 g_Wtl[4][(size_t)DIM * DIM];
__device__ __align__(256) __nv_bfloat16 g_Qh[(size_t)MTOT * DIM];
__device__ __align__(256) __nv_bfloat16 g_Ql[(size_t)MTOT * DIM];
__device__ __align__(256) __nv_bfloat16 g_Kh[(size_t)MTOT * DIM];
__device__ __align__(256) __nv_bfloat16 g_Kl[(size_t)MTOT * DIM];
__device__ __align__(256) __nv_bfloat16 g_Vh[(size_t)MTOT * DIM];
__device__ __align__(256) __nv_bfloat16 g_Vl[(size_t)MTOT * DIM];
__device__ __align__(256) __nv_bfloat16 g_Vth[(size_t)MTOT * DIM];
__device__ __align__(256) __nv_bfloat16 g_Vtl[(size_t)MTOT * DIM];
__device__ __align__(256) __nv_bfloat16 g_Oh[(size_t)MTOT * DIM];
__device__ __align__(256) __nv_bfloat16 g_Ol[(size_t)MTOT * DIM];
__device__ __align__(256) float          g_S [(size_t)BATCH * SEQ * SEQ];
__device__ __align__(256) __nv_bfloat16 g_Ph[(size_t)BATCH * SEQ * SEQ];
__device__ __align__(256) __nv_bfloat16 g_Pl[(size_t)BATCH * SEQ * SEQ];

// ---------------------------------------------------------------------------
// Helpers (arch-agnostic PTX only: cp.async / ldmatrix / mma.sync)
// ---------------------------------------------------------------------------
__device__ __forceinline__ uint32_t smem_to_u32(const void* smem_ptr) {
    uint32_t addr;
    asm("{ .reg .u64 tmp; cvta.to.shared.u64 tmp, %1; cvt.u32.u64 %0, tmp; }"
        : "=r"(addr) : "l"(smem_ptr));
    return addr;
}
#define SMEM_SWIZZLE_128B(byte_offset) \
    ((byte_offset) ^ (((byte_offset) >> 3) & 0x70))
#define CP_ASYNC_16(dst_u32, src_ptr) \
    asm volatile("cp.async.cg.shared.global [%0], [%1], 16;" \
                 :: "r"(dst_u32), "l"(src_ptr) : "memory")
#define CP_COMMIT() asm volatile("cp.async.commit_group;" ::: "memory")
#define CP_WAIT(n)  asm volatile("cp.async.wait_group %0;" :: "n"(n) : "memory")

#define LDMATRIX_X4(r0, r1, r2, r3, addr) \
    asm volatile("ldmatrix.sync.aligned.m8n8.x4.shared.b16 {%0,%1,%2,%3}, [%4];" \
                 : "=r"(r0), "=r"(r1), "=r"(r2), "=r"(r3) : "r"(addr))

#define MMA_BF16(c, a, b0, b1) \
    asm volatile("mma.sync.aligned.m16n8k16.row.col.f32.bf16.bf16.f32 " \
                 "{%0,%1,%2,%3}, {%4,%5,%6,%7}, {%8,%9}, {%0,%1,%2,%3};" \
                 : "+f"((c)[0]), "+f"((c)[1]), "+f"((c)[2]), "+f"((c)[3]) \
                 : "r"((a)[0]), "r"((a)[1]), "r"((a)[2]), "r"((a)[3]), \
                   "r"(b0), "r"(b1))

// ---------------------------------------------------------------------------
// GEMM: D[M,N] = A@B^T with 3-term bf16 split folded into K_eff = 3K.
// Tile 128x128, BK=64 bf16 (128B rows, SW128), 2-stage cp.async double buffer,
// 8 warps (4m x 2n), warp tile 32x64 m16n8k16.
// Inner loop: ALL 6 LDSMs issued before the 16 independent MMAs (hides
// ldmatrix latency behind tensor issue; 16 distinct accumulators).
// EPI: 0 = fp32 out, 1 = fp32 + bias, 2 = split bf16 hi/lo out.
// MULTI_B: blockIdx.z selects weight set / output via pointer tables.
// ---------------------------------------------------------------------------
#define TILE_BYTES 16384            // 128 rows x 128B
#define STAGE_BYTES (2 * TILE_BYTES)
#define SM_TOTAL (2 * STAGE_BYTES)  // 65536

template <int EPI, bool MULTI_B>
__global__ void __launch_bounds__(256, 2)
gemm3_kernel(const __nv_bfloat16* __restrict__ Ah, const __nv_bfloat16* __restrict__ Al,
             const __nv_bfloat16* __restrict__ Bh, const __nv_bfloat16* __restrict__ Bl,
             float* __restrict__ Cf,
             __nv_bfloat16* __restrict__ Ch, __nv_bfloat16* __restrict__ Cl,
             __nv_bfloat16* const* __restrict__ multiCh,
             __nv_bfloat16* const* __restrict__ multiCl,
             const float* __restrict__ bias,
             int K, int ldC, size_t sA, size_t sB, size_t sC)
{
    extern __shared__ char smem[];
    const uint32_t smem_u = smem_to_u32(smem);
    const int tid = threadIdx.x;
    const int lane = tid & 31;
    const int wid = tid >> 5;
    const int warp_m = wid & 3;
    const int warp_n = wid >> 2;
    const int rowBase = blockIdx.y * 128;
    const int colBase = blockIdx.x * 128;
    const size_t zA = MULTI_B ? 0 : (size_t)blockIdx.z * sA;
    const size_t zB = (size_t)blockIdx.z * sB;
    const size_t zC = MULTI_B ? 0 : (size_t)blockIdx.z * sC;
    __nv_bfloat16* ChSel = MULTI_B ? multiCh[blockIdx.z] : Ch;
    __nv_bfloat16* ClSel = MULTI_B ? multiCl[blockIdx.z] : Cl;

    const int ldr_row0 = tid >> 3;
    const int ldr_ch   = tid & 7;

    float acc[2][8][4];
#pragma unroll
    for (int i = 0; i < 2; i++)
#pragma unroll
        for (int j = 0; j < 8; j++)
#pragma unroll
            for (int e = 0; e < 4; e++) acc[i][j][e] = 0.0f;

    const int nk = K >> 6;
    const int nIter = 3 * nk;

    auto issue_load = [&](int i, int stage) {
        const int seg = i / nk;
        const int kk = (i - seg * nk) << 6;
        const __nv_bfloat16* As = ((seg == 1) ? Al : Ah) + zA;
        const __nv_bfloat16* Bs = ((seg == 2) ? Bl : Bh) + zB;
        const uint32_t aBase = smem_u + stage * STAGE_BYTES;
        const uint32_t bBase = aBase + TILE_BYTES;
#pragma unroll
        for (int p = 0; p < 4; p++) {
            const int row = ldr_row0 + p * 32;
            const uint32_t soff = SMEM_SWIZZLE_128B((uint32_t)row * 128 + ldr_ch * 16);
            CP_ASYNC_16(aBase + soff,
                        As + (size_t)(rowBase + row) * K + kk + ldr_ch * 8);
            CP_ASYNC_16(bBase + soff,
                        Bs + (size_t)(colBase + row) * K + kk + ldr_ch * 8);
        }
        CP_COMMIT();
    };

    issue_load(0, 0);

    for (int i = 0; i < nIter; i++) {
        const int stage = i & 1;
        if (i + 1 < nIter) {
            issue_load(i + 1, (i + 1) & 1);
            CP_WAIT(1);
        } else {
            CP_WAIT(0);
        }
        __syncthreads();

        const uint32_t aBase = smem_u + stage * STAGE_BYTES;
        const uint32_t bBase = aBase + TILE_BYTES;
#pragma unroll
        for (int ks = 0; ks < 4; ks++) {
            const uint32_t k2 = ks * 32;
            uint32_t a[2][4];
            uint32_t b[4][4];
            // --- issue ALL loads for this ks first ---
#pragma unroll
            for (int fm = 0; fm < 2; fm++) {
                const uint32_t row = warp_m * 32 + fm * 16 + (lane & 15);
                const uint32_t addr = aBase +
                    SMEM_SWIZZLE_128B(row * 128 + k2 + ((lane >> 4) << 4));
                LDMATRIX_X4(a[fm][0], a[fm][1], a[fm][2], a[fm][3], addr);
            }
#pragma unroll
            for (int fn2 = 0; fn2 < 4; fn2++) {
                const uint32_t n = warp_n * 64 + fn2 * 16 + (lane & 7) + ((lane >> 4) << 3);
                const uint32_t addr = bBase +
                    SMEM_SWIZZLE_128B(n * 128 + k2 + (((lane >> 3) & 1) << 4));
                LDMATRIX_X4(b[fn2][0], b[fn2][1], b[fn2][2], b[fn2][3], addr);
            }
            // --- then 16 independent MMAs ---
#pragma unroll
            for (int fn2 = 0; fn2 < 4; fn2++) {
                MMA_BF16(acc[0][fn2 * 2 + 0], a[0], b[fn2][0], b[fn2][1]);
                MMA_BF16(acc[0][fn2 * 2 + 1], a[0], b[fn2][2], b[fn2][3]);
                MMA_BF16(acc[1][fn2 * 2 + 0], a[1], b[fn2][0], b[fn2][1]);
                MMA_BF16(acc[1][fn2 * 2 + 1], a[1], b[fn2][2], b[fn2][3]);
            }
        }
        __syncthreads();
    }

    // Epilogue
    const int gid = lane >> 2;
    const int tig = lane & 3;
#pragma unroll
    for (int fm = 0; fm < 2; fm++) {
#pragma unroll
        for (int fn = 0; fn < 8; fn++) {
            const int r0 = rowBase + warp_m * 32 + fm * 16 + gid;
            const int c  = colBase + warp_n * 64 + fn * 8 + tig * 2;
            const float* ac = acc[fm][fn];
            if (EPI == 2) {
                __nv_bfloat162 h0 = __floats2bfloat162_rn(ac[0], ac[1]);
                float2 hf0 = __bfloat1622float2(h0);
                __nv_bfloat162 l0 = __floats2bfloat162_rn(ac[0] - hf0.x, ac[1] - hf0.y);
                __nv_bfloat162 h1 = __floats2bfloat162_rn(ac[2], ac[3]);
                float2 hf1 = __bfloat1622float2(h1);
                __nv_bfloat162 l1 = __floats2bfloat162_rn(ac[2] - hf1.x, ac[3] - hf1.y);
                *(uint32_t*)(ChSel + zC + (size_t)r0 * ldC + c)       = *(uint32_t*)&h0;
                *(uint32_t*)(ClSel + zC + (size_t)r0 * ldC + c)       = *(uint32_t*)&l0;
                *(uint32_t*)(ChSel + zC + (size_t)(r0 + 8) * ldC + c) = *(uint32_t*)&h1;
                *(uint32_t*)(ClSel + zC + (size_t)(r0 + 8) * ldC + c) = *(uint32_t*)&l1;
            } else {
                float2 v0 = make_float2(ac[0], ac[1]);
                float2 v1 = make_float2(ac[2], ac[3]);
                if (EPI == 1) {
                    const float b0 = bias[c], b1 = bias[c + 1];
                    v0.x += b0; v0.y += b1;
                    v1.x += b0; v1.y += b1;
                }
                *(float2*)(Cf + zC + (size_t)r0 * ldC + c)       = v0;
                *(float2*)(Cf + zC + (size_t)(r0 + 8) * ldC + c) = v1;
            }
        }
    }
}

// Pointer tables (device) for fused multi-output launches
__device__ __nv_bfloat16* g_qkvCh[3];
__device__ __nv_bfloat16* g_qkvCl[3];
__device__ const float*   g_wIn[4];
__global__ void init_ptrs_kernel(const float* Wq, const float* Wk,
                                 const float* Wv, const float* Wp) {
    g_qkvCh[0] = g_Qh; g_qkvCh[1] = g_Kh; g_qkvCh[2] = g_Vh;
    g_qkvCl[0] = g_Ql; g_qkvCl[1] = g_Kl; g_qkvCl[2] = g_Vl;
    g_wIn[0] = Wq; g_wIn[1] = Wk; g_wIn[2] = Wv; g_wIn[3] = Wp;
}

// ---------------------------------------------------------------------------
// fp32 -> bf16 hi/lo split (elementwise)
// ---------------------------------------------------------------------------
__global__ void __launch_bounds__(256)
split_fp32_kernel(const float* __restrict__ x,
                  __nv_bfloat16* __restrict__ h, __nv_bfloat16* __restrict__ l)
{
    size_t i = ((size_t)blockIdx.x * 256 + threadIdx.x) * 4;
    float4 v = *(const float4*)(x + i);
    float vv[4] = {v.x, v.y, v.z, v.w};
    __nv_bfloat16 hh[4], ll[4];
#pragma unroll
    for (int j = 0; j < 4; j++) {
        hh[j] = __float2bfloat16(vv[j]);
        ll[j] = __float2bfloat16(vv[j] - __bfloat162float(hh[j]));
    }
    *(uint2*)(h + i) = *(uint2*)hh;
    *(uint2*)(l + i) = *(uint2*)ll;
}

// ---------------------------------------------------------------------------
// Transpose + split ALL FOUR weight matrices in one launch (z selects).
// ---------------------------------------------------------------------------
__global__ void __launch_bounds__(256)
transW_all_kernel(__nv_bfloat16* __restrict__ thB, __nv_bfloat16* __restrict__ tlB)
{
    const float* W = g_wIn[blockIdx.z];
    __nv_bfloat16* th = thB + (size_t)blockIdx.z * DIM * DIM;
    __nv_bfloat16* tl = tlB + (size_t)blockIdx.z * DIM * DIM;
    __shared__ float t[32][33];
    const int tx = threadIdx.x, ty = threadIdx.y;
    const int x = blockIdx.x * 32 + tx;
    const int y0 = blockIdx.y * 32;
#pragma unroll
    for (int p = 0; p < 4; p++)
        t[ty + 8 * p][tx] = W[(size_t)(y0 + ty + 8 * p) * DIM + x];
    __syncthreads();
    const int ox = blockIdx.y * 32 + tx;
    const int oy0 = blockIdx.x * 32;
#pragma unroll
    for (int p = 0; p < 4; p++) {
        float v = t[tx][ty + 8 * p];
        __nv_bfloat16 h = __float2bfloat16(v);
        __nv_bfloat16 l = __float2bfloat16(v - __bfloat162float(h));
        th[(size_t)(oy0 + ty + 8 * p) * DIM + ox] = h;
        tl[(size_t)(oy0 + ty + 8 * p) * DIM + ox] = l;
    }
}

// ---------------------------------------------------------------------------
// Transpose bf16 pair per batch: V [SEQ,DIM] -> Vt [DIM,SEQ]
// ---------------------------------------------------------------------------
__global__ void __launch_bounds__(256)
transV_kernel(const __nv_bfloat16* __restrict__ ih, const __nv_bfloat16* __restrict__ il,
              __nv_bfloat16* __restrict__ oh, __nv_bfloat16* __restrict__ ol)
{
    __shared__ __nv_bfloat16 t0[32][33];
    __shared__ __nv_bfloat16 t1[32][33];
    const size_t zin = (size_t)blockIdx.z * SEQ * DIM;
    const int tx = threadIdx.x, ty = threadIdx.y;
    const int x = blockIdx.x * 32 + tx;
    const int y0 = blockIdx.y * 32;
#pragma unroll
    for (int p = 0; p < 4; p++) {
        t0[ty + 8 * p][tx] = ih[zin + (size_t)(y0 + ty + 8 * p) * DIM + x];
        t1[ty + 8 * p][tx] = il[zin + (size_t)(y0 + ty + 8 * p) * DIM + x];
    }
    __syncthreads();
    const int ox = blockIdx.y * 32 + tx;
    const int oy0 = blockIdx.x * 32;
#pragma unroll
    for (int p = 0; p < 4; p++) {
        oh[zin + (size_t)(oy0 + ty + 8 * p) * SEQ + ox] = t0[tx][ty + 8 * p];
        ol[zin + (size_t)(oy0 + ty + 8 * p) * SEQ + ox] = t1[tx][ty + 8 * p];
    }
}

// ---------------------------------------------------------------------------
// Row softmax (SEQ=2048 cols) in log2 domain; emits split-bf16 P
// ---------------------------------------------------------------------------
__global__ void __launch_bounds__(256)
softmax_split_kernel(const float* __restrict__ S,
                     __nv_bfloat16* __restrict__ Ph, __nv_bfloat16* __restrict__ Pl,
                     float scale_log2e)
{
    const size_t row = blockIdx.x;
    const float* p = S + row * SEQ;
    const int tid = threadIdx.x;

    float vals[8];
    float lmax = -INFINITY;
#pragma unroll
    for (int i = 0; i < 8; i++) {
        float v = p[tid + i * 256] * scale_log2e;
        vals[i] = v;
        lmax = fmaxf(lmax, v);
    }
    __shared__ float red[8];
#pragma unroll
    for (int o = 16; o > 0; o >>= 1)
        lmax = fmaxf(lmax, __shfl_xor_sync(0xffffffffu, lmax, o));
    if ((tid & 31) == 0) red[tid >> 5] = lmax;
    __syncthreads();
    float m = red[0];
#pragma unroll
    for (int w = 1; w < 8; w++) m = fmaxf(m, red[w]);
    __syncthreads();

    float lsum = 0.0f;
#pragma unroll
    for (int i = 0; i < 8; i++) {
        vals[i] = exp2f(vals[i] - m);
        lsum += vals[i];
    }
#pragma unroll
    for (int o = 16; o > 0; o >>= 1)
        lsum += __shfl_xor_sync(0xffffffffu, lsum, o);
    if ((tid & 31) == 0) red[tid >> 5] = lsum;
    __syncthreads();
    float tot = 0.0f;
#pragma unroll
    for (int w = 0; w < 8; w++) tot += red[w];
    const float rinv = 1.0f / tot;

#pragma unroll
    for (int i = 0; i < 8; i++) {
        float v = vals[i] * rinv;
        __nv_bfloat16 h = __float2bfloat16(v);
        __nv_bfloat16 l = __float2bfloat16(v - __bfloat162float(h));
        Ph[row * SEQ + tid + i * 256] = h;
        Pl[row * SEQ + tid + i * 256] = l;
    }
}

// ---------------------------------------------------------------------------
// kernel_launch
// ---------------------------------------------------------------------------
extern "C" void kernel_launch(void* const* d_in, const int* in_sizes, int n_in,
                              void* d_out, int out_size)
{
    (void)in_sizes; (void)n_in; (void)out_size;
    const float* x  = (const float*)d_in[0];
    const float* Wq = (const float*)d_in[1];
    const float* Wk = (const float*)d_in[2];
    const float* Wv = (const float*)d_in[3];
    const float* Wp = (const float*)d_in[4];
    const float* bp = (const float*)d_in[5];
    float* out = (float*)d_out;

    __nv_bfloat16 *xh, *xl, *Wth, *Wtl, *Qh, *Ql, *Kh, *Kl, *Vh, *Vl,
                  *Vth, *Vtl, *Oh, *Ol, *Ph, *Pl;
    float* S;
    __nv_bfloat16 **qkvCh, **qkvCl;
    cudaGetSymbolAddress((void**)&xh, g_xh);
    cudaGetSymbolAddress((void**)&xl, g_xl);
    cudaGetSymbolAddress((void**)&Wth, g_Wth);
    cudaGetSymbolAddress((void**)&Wtl, g_Wtl);
    cudaGetSymbolAddress((void**)&Qh, g_Qh);
    cudaGetSymbolAddress((void**)&Ql, g_Ql);
    cudaGetSymbolAddress((void**)&Kh, g_Kh);
    cudaGetSymbolAddress((void**)&Kl, g_Kl);
    cudaGetSymbolAddress((void**)&Vh, g_Vh);
    cudaGetSymbolAddress((void**)&Vl, g_Vl);
    cudaGetSymbolAddress((void**)&Vth, g_Vth);
    cudaGetSymbolAddress((void**)&Vtl, g_Vtl);
    cudaGetSymbolAddress((void**)&Oh, g_Oh);
    cudaGetSymbolAddress((void**)&Ol, g_Ol);
    cudaGetSymbolAddress((void**)&S, g_S);
    cudaGetSymbolAddress((void**)&Ph, g_Ph);
    cudaGetSymbolAddress((void**)&Pl, g_Pl);
    cudaGetSymbolAddress((void**)&qkvCh, g_qkvCh);
    cudaGetSymbolAddress((void**)&qkvCl, g_qkvCl);

    const size_t wstep = (size_t)DIM * DIM;

    cudaFuncSetAttribute(gemm3_kernel<0, false>, cudaFuncAttributeMaxDynamicSharedMemorySize, SM_TOTAL);
    cudaFuncSetAttribute(gemm3_kernel<1, false>, cudaFuncAttributeMaxDynamicSharedMemorySize, SM_TOTAL);
    cudaFuncSetAttribute(gemm3_kernel<2, false>, cudaFuncAttributeMaxDynamicSharedMemorySize, SM_TOTAL);
    cudaFuncSetAttribute(gemm3_kernel<2, true>,  cudaFuncAttributeMaxDynamicSharedMemorySize, SM_TOTAL);

    // Launch 1: pointer tables
    init_ptrs_kernel<<<1, 1>>>(Wq, Wk, Wv, Wp);

    // Launch 2: transpose + split all four weights
    {
        dim3 g(DIM / 32, DIM / 32, 4), b(32, 8);
        transW_all_kernel<<<g, b>>>(Wth, Wtl);
    }

    // Launch 3: split x
    split_fp32_kernel<<<(size_t)MTOT * DIM / 1024, 256>>>(x, xh, xl);

    // Launch 4: fused Q/K/V projections
    {
        dim3 g(DIM / 128, MTOT / 128, 3);
        gemm3_kernel<2, true><<<g, 256, SM_TOTAL>>>(
            xh, xl, Wth, Wtl,
            nullptr, nullptr, nullptr, qkvCh, qkvCl, nullptr,
            DIM, DIM, 0, wstep, 0);
    }

    // Launch 5 (ncu target): S = Q @ K^T per batch
    {
        dim3 g(SEQ / 128, SEQ / 128, BATCH);
        gemm3_kernel<0, false><<<g, 256, SM_TOTAL>>>(
            Qh, Ql, Kh, Kl,
            S, nullptr, nullptr, nullptr, nullptr, nullptr,
            DIM, SEQ,
            (size_t)SEQ * DIM, (size_t)SEQ * DIM, (size_t)SEQ * SEQ);
    }

    // softmax (log2 domain) -> split bf16 P
    softmax_split_kernel<<<MTOT, 256>>>(S, Ph, Pl, 0.03125f * 1.4426950408889634f);

    // transpose V per batch -> Vt [DIM, SEQ]
    {
        dim3 g(DIM / 32, SEQ / 32, BATCH), b(32, 8);
        transV_kernel<<<g, b>>>(Vh, Vl, Vth, Vtl);
    }

    // O = P @ V per batch -> split bf16 O
    {
        dim3 g(DIM / 128, SEQ / 128, BATCH);
        gemm3_kernel<2, false><<<g, 256, SM_TOTAL>>>(
            Ph, Pl, Vth, Vtl,
            nullptr, Oh, Ol, nullptr, nullptr, nullptr,
            SEQ, DIM,
            (size_t)SEQ * SEQ, (size_t)DIM * SEQ, (size_t)SEQ * DIM);
    }

    // out = O @ Wp^T + bp (fp32)
    {
        dim3 g(DIM / 128, MTOT / 128, 1);
        gemm3_kernel<1, false><<<g, 256, SM_TOTAL>>>(
            Oh, Ol, Wth + 3 * wstep, Wtl + 3 * wstep,
            out, nullptr, nullptr, nullptr, nullptr, bp,
            DIM, DIM, 0, 0, 0);
    }
}

// round 8
// speedup vs baseline: 2.8520x; 2.6986x over previous
#include <cuda_runtime.h>
#include <cuda_fp16.h>
#include <stdint.h>
#include <math.h>

#define BATCH 8
#define SEQ   2048
#define DIM   1024
#define MTOT  (BATCH * SEQ)

// ---------------------------------------------------------------------------
// Static device scratch (allocation-free contract).
// ---------------------------------------------------------------------------
__device__ __align__(256) __half g_xH[(size_t)MTOT * DIM];
__device__ __align__(256) __half g_WtH[4][(size_t)DIM * DIM];
__device__ __align__(256) __half g_Q[(size_t)MTOT * DIM];
__device__ __align__(256) __half g_K[(size_t)MTOT * DIM];
__device__ __align__(256) __half g_V[(size_t)MTOT * DIM];
__device__ __align__(256) __half g_Vt[(size_t)MTOT * DIM];
__device__ __align__(256) __half g_O[(size_t)MTOT * DIM];
__device__ __align__(256) float  g_S[(size_t)BATCH * SEQ * SEQ];
__device__ __align__(256) __half g_P[(size_t)BATCH * SEQ * SEQ];

// ---------------------------------------------------------------------------
// Helpers (arch-agnostic PTX only: cp.async / ldmatrix / mma.sync)
// ---------------------------------------------------------------------------
__device__ __forceinline__ uint32_t smem_to_u32(const void* smem_ptr) {
    uint32_t addr;
    asm("{ .reg .u64 tmp; cvta.to.shared.u64 tmp, %1; cvt.u32.u64 %0, tmp; }"
        : "=r"(addr) : "l"(smem_ptr));
    return addr;
}
#define SMEM_SWIZZLE_128B(byte_offset) \
    ((byte_offset) ^ (((byte_offset) >> 3) & 0x70))
#define CP_ASYNC_16(dst_u32, src_ptr) \
    asm volatile("cp.async.cg.shared.global [%0], [%1], 16;" \
                 :: "r"(dst_u32), "l"(src_ptr) : "memory")
#define CP_COMMIT() asm volatile("cp.async.commit_group;" ::: "memory")
#define CP_WAIT(n)  asm volatile("cp.async.wait_group %0;" :: "n"(n) : "memory")

#define LDMATRIX_X4(r0, r1, r2, r3, addr) \
    asm volatile("ldmatrix.sync.aligned.m8n8.x4.shared.b16 {%0,%1,%2,%3}, [%4];" \
                 : "=r"(r0), "=r"(r1), "=r"(r2), "=r"(r3) : "r"(addr))

#define MMA_F16(c, a, b0, b1) \
    asm volatile("mma.sync.aligned.m16n8k16.row.col.f32.f16.f16.f32 " \
                 "{%0,%1,%2,%3}, {%4,%5,%6,%7}, {%8,%9}, {%0,%1,%2,%3};" \
                 : "+f"((c)[0]), "+f"((c)[1]), "+f"((c)[2]), "+f"((c)[3]) \
                 : "r"((a)[0]), "r"((a)[1]), "r"((a)[2]), "r"((a)[3]), \
                   "r"(b0), "r"(b1))

// ---------------------------------------------------------------------------
// GEMM: D[M,N] = A@B^T, single-pass fp16 inputs, fp32 accumulate.
//   A: [M,K] K-major fp16 ; B: [N,K] K-major fp16
// Tile 128x128, BK=64 (128B rows, SW128), 2-stage cp.async double buffer,
// 8 warps (4m x 2n), warp tile 32x64 via m16n8k16 HMMA.
// EPI: 0 = fp32 out, 1 = fp32 + bias, 2 = fp16 out.
// MULTI_B: blockIdx.z selects weight set / output via pointer tables.
// ---------------------------------------------------------------------------
#define TILE_BYTES 16384            // 128 rows x 128B
#define STAGE_BYTES (2 * TILE_BYTES)
#define SM_TOTAL (2 * STAGE_BYTES)  // 65536

template <int EPI, bool MULTI_B>
__global__ void __launch_bounds__(256, 2)
gemmh_kernel(const __half* __restrict__ A, const __half* __restrict__ B,
             float* __restrict__ Cf, __half* __restrict__ Ch,
             __half* const* __restrict__ multiCh,
             const float* __restrict__ bias,
             int K, int ldC, size_t sA, size_t sB, size_t sC)
{
    extern __shared__ char smem[];
    const uint32_t smem_u = smem_to_u32(smem);
    const int tid = threadIdx.x;
    const int lane = tid & 31;
    const int wid = tid >> 5;
    const int warp_m = wid & 3;
    const int warp_n = wid >> 2;
    const int rowBase = blockIdx.y * 128;
    const int colBase = blockIdx.x * 128;
    const size_t zA = MULTI_B ? 0 : (size_t)blockIdx.z * sA;
    const size_t zB = (size_t)blockIdx.z * sB;
    const size_t zC = MULTI_B ? 0 : (size_t)blockIdx.z * sC;
    __half* ChSel = MULTI_B ? multiCh[blockIdx.z] : Ch;

    const int ldr_row0 = tid >> 3;
    const int ldr_ch   = tid & 7;

    float acc[2][8][4];
#pragma unroll
    for (int i = 0; i < 2; i++)
#pragma unroll
        for (int j = 0; j < 8; j++)
#pragma unroll
            for (int e = 0; e < 4; e++) acc[i][j][e] = 0.0f;

    const int nIter = K >> 6;

    auto issue_load = [&](int i, int stage) {
        const int kk = i << 6;
        const __half* As = A + zA;
        const __half* Bs = B + zB;
        const uint32_t aBase = smem_u + stage * STAGE_BYTES;
        const uint32_t bBase = aBase + TILE_BYTES;
#pragma unroll
        for (int p = 0; p < 4; p++) {
            const int row = ldr_row0 + p * 32;
            const uint32_t soff = SMEM_SWIZZLE_128B((uint32_t)row * 128 + ldr_ch * 16);
            CP_ASYNC_16(aBase + soff,
                        As + (size_t)(rowBase + row) * K + kk + ldr_ch * 8);
            CP_ASYNC_16(bBase + soff,
                        Bs + (size_t)(colBase + row) * K + kk + ldr_ch * 8);
        }
        CP_COMMIT();
    };

    issue_load(0, 0);

    for (int i = 0; i < nIter; i++) {
        const int stage = i & 1;
        if (i + 1 < nIter) {
            issue_load(i + 1, (i + 1) & 1);
            CP_WAIT(1);
        } else {
            CP_WAIT(0);
        }
        __syncthreads();

        const uint32_t aBase = smem_u + stage * STAGE_BYTES;
        const uint32_t bBase = aBase + TILE_BYTES;
#pragma unroll
        for (int ks = 0; ks < 4; ks++) {
            const uint32_t k2 = ks * 32;
            uint32_t a[2][4];
            uint32_t b[4][4];
#pragma unroll
            for (int fm = 0; fm < 2; fm++) {
                const uint32_t row = warp_m * 32 + fm * 16 + (lane & 15);
                const uint32_t addr = aBase +
                    SMEM_SWIZZLE_128B(row * 128 + k2 + ((lane >> 4) << 4));
                LDMATRIX_X4(a[fm][0], a[fm][1], a[fm][2], a[fm][3], addr);
            }
#pragma unroll
            for (int fn2 = 0; fn2 < 4; fn2++) {
                const uint32_t n = warp_n * 64 + fn2 * 16 + (lane & 7) + ((lane >> 4) << 3);
                const uint32_t addr = bBase +
                    SMEM_SWIZZLE_128B(n * 128 + k2 + (((lane >> 3) & 1) << 4));
                LDMATRIX_X4(b[fn2][0], b[fn2][1], b[fn2][2], b[fn2][3], addr);
            }
#pragma unroll
            for (int fn2 = 0; fn2 < 4; fn2++) {
                MMA_F16(acc[0][fn2 * 2 + 0], a[0], b[fn2][0], b[fn2][1]);
                MMA_F16(acc[0][fn2 * 2 + 1], a[0], b[fn2][2], b[fn2][3]);
                MMA_F16(acc[1][fn2 * 2 + 0], a[1], b[fn2][0], b[fn2][1]);
                MMA_F16(acc[1][fn2 * 2 + 1], a[1], b[fn2][2], b[fn2][3]);
            }
        }
        __syncthreads();
    }

    // Epilogue
    const int gid = lane >> 2;
    const int tig = lane & 3;
#pragma unroll
    for (int fm = 0; fm < 2; fm++) {
#pragma unroll
        for (int fn = 0; fn < 8; fn++) {
            const int r0 = rowBase + warp_m * 32 + fm * 16 + gid;
            const int c  = colBase + warp_n * 64 + fn * 8 + tig * 2;
            const float* ac = acc[fm][fn];
            if (EPI == 2) {
                __half2 h0 = __floats2half2_rn(ac[0], ac[1]);
                __half2 h1 = __floats2half2_rn(ac[2], ac[3]);
                *(uint32_t*)(ChSel + zC + (size_t)r0 * ldC + c)       = *(uint32_t*)&h0;
                *(uint32_t*)(ChSel + zC + (size_t)(r0 + 8) * ldC + c) = *(uint32_t*)&h1;
            } else {
                float2 v0 = make_float2(ac[0], ac[1]);
                float2 v1 = make_float2(ac[2], ac[3]);
                if (EPI == 1) {
                    const float b0 = bias[c], b1 = bias[c + 1];
                    v0.x += b0; v0.y += b1;
                    v1.x += b0; v1.y += b1;
                }
                *(float2*)(Cf + zC + (size_t)r0 * ldC + c)       = v0;
                *(float2*)(Cf + zC + (size_t)(r0 + 8) * ldC + c) = v1;
            }
        }
    }
}

// Pointer tables (device) for fused multi-output launches
__device__ __half*       g_qkvC[3];
__device__ const float*  g_wIn[4];
__global__ void init_ptrs_kernel(const float* Wq, const float* Wk,
                                 const float* Wv, const float* Wp) {
    g_qkvC[0] = g_Q; g_qkvC[1] = g_K; g_qkvC[2] = g_V;
    g_wIn[0] = Wq; g_wIn[1] = Wk; g_wIn[2] = Wv; g_wIn[3] = Wp;
}

// ---------------------------------------------------------------------------
// fp32 -> fp16 convert (elementwise)
// ---------------------------------------------------------------------------
__global__ void __launch_bounds__(256)
convert_fp16_kernel(const float* __restrict__ x, __half* __restrict__ h)
{
    size_t i = ((size_t)blockIdx.x * 256 + threadIdx.x) * 4;
    float4 v = *(const float4*)(x + i);
    __half2 a = __floats2half2_rn(v.x, v.y);
    __half2 b = __floats2half2_rn(v.z, v.w);
    *(uint2*)(h + i) = make_uint2(*(uint32_t*)&a, *(uint32_t*)&b);
}

// ---------------------------------------------------------------------------
// Transpose + convert ALL FOUR weight matrices in one launch (z selects).
// Wt[e,d] = W[d,e] as fp16.
// ---------------------------------------------------------------------------
__global__ void __launch_bounds__(256)
transW_all_kernel(__half* __restrict__ thB)
{
    const float* W = g_wIn[blockIdx.z];
    __half* th = thB + (size_t)blockIdx.z * DIM * DIM;
    __shared__ float t[32][33];
    const int tx = threadIdx.x, ty = threadIdx.y;
    const int x = blockIdx.x * 32 + tx;
    const int y0 = blockIdx.y * 32;
#pragma unroll
    for (int p = 0; p < 4; p++)
        t[ty + 8 * p][tx] = W[(size_t)(y0 + ty + 8 * p) * DIM + x];
    __syncthreads();
    const int ox = blockIdx.y * 32 + tx;
    const int oy0 = blockIdx.x * 32;
#pragma unroll
    for (int p = 0; p < 4; p++)
        th[(size_t)(oy0 + ty + 8 * p) * DIM + ox] = __float2half_rn(t[tx][ty + 8 * p]);
}

// ---------------------------------------------------------------------------
// Transpose fp16 per batch: V [SEQ,DIM] -> Vt [DIM,SEQ]
// ---------------------------------------------------------------------------
__global__ void __launch_bounds__(256)
transV_kernel(const __half* __restrict__ iv, __half* __restrict__ ov)
{
    __shared__ __half t0[32][33];
    const size_t zin = (size_t)blockIdx.z * SEQ * DIM;
    const int tx = threadIdx.x, ty = threadIdx.y;
    const int x = blockIdx.x * 32 + tx;
    const int y0 = blockIdx.y * 32;
#pragma unroll
    for (int p = 0; p < 4; p++)
        t0[ty + 8 * p][tx] = iv[zin + (size_t)(y0 + ty + 8 * p) * DIM + x];
    __syncthreads();
    const int ox = blockIdx.y * 32 + tx;
    const int oy0 = blockIdx.x * 32;
#pragma unroll
    for (int p = 0; p < 4; p++)
        ov[zin + (size_t)(oy0 + ty + 8 * p) * SEQ + ox] = t0[tx][ty + 8 * p];
}

// ---------------------------------------------------------------------------
// Row softmax (SEQ=2048 cols) in log2 domain; emits fp16 P
// ---------------------------------------------------------------------------
__global__ void __launch_bounds__(256)
softmax_kernel(const float* __restrict__ S, __half* __restrict__ P,
               float scale_log2e)
{
    const size_t row = blockIdx.x;
    const float* p = S + row * SEQ;
    const int tid = threadIdx.x;

    float vals[8];
    float lmax = -INFINITY;
#pragma unroll
    for (int i = 0; i < 8; i++) {
        float v = p[tid + i * 256] * scale_log2e;
        vals[i] = v;
        lmax = fmaxf(lmax, v);
    }
    __shared__ float red[8];
#pragma unroll
    for (int o = 16; o > 0; o >>= 1)
        lmax = fmaxf(lmax, __shfl_xor_sync(0xffffffffu, lmax, o));
    if ((tid & 31) == 0) red[tid >> 5] = lmax;
    __syncthreads();
    float m = red[0];
#pragma unroll
    for (int w = 1; w < 8; w++) m = fmaxf(m, red[w]);
    __syncthreads();

    float lsum = 0.0f;
#pragma unroll
    for (int i = 0; i < 8; i++) {
        vals[i] = exp2f(vals[i] - m);
        lsum += vals[i];
    }
#pragma unroll
    for (int o = 16; o > 0; o >>= 1)
        lsum += __shfl_xor_sync(0xffffffffu, lsum, o);
    if ((tid & 31) == 0) red[tid >> 5] = lsum;
    __syncthreads();
    float tot = 0.0f;
#pragma unroll
    for (int w = 0; w < 8; w++) tot += red[w];
    const float rinv = 1.0f / tot;

#pragma unroll
    for (int i = 0; i < 8; i++)
        P[row * SEQ + tid + i * 256] = __float2half_rn(vals[i] * rinv);
}

// ---------------------------------------------------------------------------
// kernel_launch
// ---------------------------------------------------------------------------
extern "C" void kernel_launch(void* const* d_in, const int* in_sizes, int n_in,
                              void* d_out, int out_size)
{
    (void)in_sizes; (void)n_in; (void)out_size;
    const float* x  = (const float*)d_in[0];
    const float* Wq = (const float*)d_in[1];
    const float* Wk = (const float*)d_in[2];
    const float* Wv = (const float*)d_in[3];
    const float* Wp = (const float*)d_in[4];
    const float* bp = (const float*)d_in[5];
    float* out = (float*)d_out;

    __half *xH, *WtH, *Q, *K, *V, *Vt, *O, *P;
    float* S;
    __half** qkvC;
    cudaGetSymbolAddress((void**)&xH, g_xH);
    cudaGetSymbolAddress((void**)&WtH, g_WtH);
    cudaGetSymbolAddress((void**)&Q, g_Q);
    cudaGetSymbolAddress((void**)&K, g_K);
    cudaGetSymbolAddress((void**)&V, g_V);
    cudaGetSymbolAddress((void**)&Vt, g_Vt);
    cudaGetSymbolAddress((void**)&O, g_O);
    cudaGetSymbolAddress((void**)&S, g_S);
    cudaGetSymbolAddress((void**)&P, g_P);
    cudaGetSymbolAddress((void**)&qkvC, g_qkvC);

    const size_t wstep = (size_t)DIM * DIM;

    cudaFuncSetAttribute(gemmh_kernel<0, false>, cudaFuncAttributeMaxDynamicSharedMemorySize, SM_TOTAL);
    cudaFuncSetAttribute(gemmh_kernel<1, false>, cudaFuncAttributeMaxDynamicSharedMemorySize, SM_TOTAL);
    cudaFuncSetAttribute(gemmh_kernel<2, false>, cudaFuncAttributeMaxDynamicSharedMemorySize, SM_TOTAL);
    cudaFuncSetAttribute(gemmh_kernel<2, true>,  cudaFuncAttributeMaxDynamicSharedMemorySize, SM_TOTAL);

    // Launch 1: pointer tables
    init_ptrs_kernel<<<1, 1>>>(Wq, Wk, Wv, Wp);

    // Launch 2: transpose + convert all four weights
    {
        dim3 g(DIM / 32, DIM / 32, 4), b(32, 8);
        transW_all_kernel<<<g, b>>>(WtH);
    }

    // Launch 3: convert x -> fp16
    convert_fp16_kernel<<<(size_t)MTOT * DIM / 1024, 256>>>(x, xH);

    // Launch 4: fused Q/K/V projections (fp16 out)
    {
        dim3 g(DIM / 128, MTOT / 128, 3);
        gemmh_kernel<2, true><<<g, 256, SM_TOTAL>>>(
            xH, WtH, nullptr, nullptr, qkvC, nullptr,
            DIM, DIM, 0, wstep, 0);
    }

    // Launch 5 (ncu target): S = Q @ K^T per batch (fp32 out)
    {
        dim3 g(SEQ / 128, SEQ / 128, BATCH);
        gemmh_kernel<0, false><<<g, 256, SM_TOTAL>>>(
            Q, K, S, nullptr, nullptr, nullptr,
            DIM, SEQ,
            (size_t)SEQ * DIM, (size_t)SEQ * DIM, (size_t)SEQ * SEQ);
    }

    // softmax (log2 domain) -> fp16 P
    softmax_kernel<<<MTOT, 256>>>(S, P, 0.03125f * 1.4426950408889634f);

    // transpose V per batch -> Vt [DIM, SEQ]
    {
        dim3 g(DIM / 32, SEQ / 32, BATCH), b(32, 8);
        transV_kernel<<<g, b>>>(V, Vt);
    }

    // O = P @ V per batch (fp16 out)
    {
        dim3 g(DIM / 128, SEQ / 128, BATCH);
        gemmh_kernel<2, false><<<g, 256, SM_TOTAL>>>(
            P, Vt, nullptr, O, nullptr, nullptr,
            SEQ, DIM,
            (size_t)SEQ * SEQ, (size_t)DIM * SEQ, (size_t)SEQ * DIM);
    }

    // out = O @ Wp^T + bp (fp32)
    {
        dim3 g(DIM / 128, MTOT / 128, 1);
        gemmh_kernel<1, false><<<g, 256, SM_TOTAL>>>(
            O, WtH + 3 * wstep, out, nullptr, nullptr, bp,
            DIM, DIM, 0, 0, 0);
    }
}